// round 5
// baseline (speedup 1.0000x reference)
#include <cuda_runtime.h>
#include <cuda_fp16.h>
#include <cstdint>

#define NTOK 32768
#define DIM  1024
#define HID  512
#define NEXP 8
#define TILE_T 128
#define MAXTILES 264   // 32768/128 + 8

// ---------------- scratch (device globals; no allocations allowed) ----------
__device__ int   g_sel[NTOK];
__device__ int   g_blockHist[128][8];
__device__ int   g_blockOff[128][8];
__device__ int   g_count[8];
__device__ int   g_padBase[8];
__device__ int   g_numTiles;
__device__ int   g_tileExpert[MAXTILES];
__device__ int   g_tileBase[MAXTILES];
__device__ int   g_tileValid[MAXTILES];
__device__ int   g_tileRange[9];
__device__ int   g_perm[NTOK + NEXP * TILE_T];
__device__ float g_scores[NTOK + NEXP * TILE_T];
__device__ float g_scorePart[(size_t)MAXTILES * 4 * 128];
__device__ float g_max[8];
__device__ float g_sum[8];
__device__ float g_partial[(size_t)MAXTILES * DIM];
// inputs converted to fp16 (written by k_gate)
__device__ __half g_xh[(size_t)NTOK * DIM];
// W1 converted to fp16, TRANSPOSED to [E][H][D]
__device__ __half g_w1h[(size_t)NEXP * HID * DIM];

// ---------------- PTX helpers (all sm_80-era; no 'a' features) --------------
__device__ __forceinline__ uint32_t smem_u32(const void* p) {
    uint32_t a;
    asm("{ .reg .u64 t; cvta.to.shared.u64 t, %1; cvt.u32.u64 %0, t; }" : "=r"(a) : "l"(p));
    return a;
}
#define SW128(o) (((uint32_t)(o)) ^ ((((uint32_t)(o)) >> 3) & 0x70))

#define CPA16(dst, src) \
    asm volatile("cp.async.cg.shared.global [%0], [%1], 16;" :: "r"(dst), "l"(src))

#define LDSM4(r, addr) \
    asm volatile("ldmatrix.sync.aligned.m8n8.x4.shared.b16 {%0,%1,%2,%3}, [%4];" \
        : "=r"((r)[0]), "=r"((r)[1]), "=r"((r)[2]), "=r"((r)[3]) : "r"(addr))
#define LDSM2(r, addr) \
    asm volatile("ldmatrix.sync.aligned.m8n8.x2.shared.b16 {%0,%1}, [%2];" \
        : "=r"((r)[0]), "=r"((r)[1]) : "r"(addr))

#define MMA_F16(d, a, b) \
    asm volatile("mma.sync.aligned.m16n8k16.row.col.f32.f16.f16.f32 " \
        "{%0,%1,%2,%3}, {%4,%5,%6,%7}, {%8,%9}, {%0,%1,%2,%3};" \
        : "+f"((d)[0]), "+f"((d)[1]), "+f"((d)[2]), "+f"((d)[3]) \
        : "r"((a)[0]), "r"((a)[1]), "r"((a)[2]), "r"((a)[3]), \
          "r"((b)[0]), "r"((b)[1]))

// ---------------- K0: convert + transpose W1 to fp16 [E][H][D] ---------------
__global__ void k_cvtW(const float* __restrict__ W1) {
    __shared__ float t[32][33];
    int e = blockIdx.z, db = blockIdx.x, hb = blockIdx.y;
    int tx = threadIdx.x, ty = threadIdx.y;  // 32 x 8
    const float* src = W1 + ((size_t)e * DIM + db * 32) * HID + hb * 32;
#pragma unroll
    for (int j = 0; j < 4; j++)
        t[ty + j * 8][tx] = src[(size_t)(ty + j * 8) * HID + tx];
    __syncthreads();
#pragma unroll
    for (int j = 0; j < 4; j++) {
        float v = t[tx][ty + j * 8];
        size_t o = ((size_t)e * HID + hb * 32 + ty + j * 8) * DIM + db * 32 + tx;
        g_w1h[o] = __float2half_rn(v);
    }
}

// ---------------- K1: gate + argmax + histogram + x->fp16 --------------------
__global__ void k_gate(const float* __restrict__ x, const float* __restrict__ gw) {
    __shared__ float sG[NEXP * DIM];
    __shared__ int sHist[8];
    int tid = threadIdx.x;
    if (tid < 8) sHist[tid] = 0;
    float4* sG4 = (float4*)sG;
    const float4* g4 = (const float4*)gw;
#pragma unroll
    for (int i = 0; i < 8; i++) sG4[tid + i * 256] = g4[tid + i * 256];
    __syncthreads();

    int warp = tid >> 5, lane = tid & 31;
    int base = blockIdx.x * 256 + warp * 32;
    for (int it = 0; it < 32; it++) {
        int n = base + it;
        const float* xr = x + (size_t)n * DIM;
        __half* xhr = g_xh + (size_t)n * DIM;
        float acc[8];
#pragma unroll
        for (int e = 0; e < 8; e++) acc[e] = 0.f;
        for (int k = 0; k < 32; k++) {
            int dd = lane + k * 32;
            float xv = xr[dd];
            xhr[dd] = __float2half_rn(xv);    // fused conversion
#pragma unroll
            for (int e = 0; e < 8; e++) acc[e] = fmaf(xv, sG[e * DIM + dd], acc[e]);
        }
#pragma unroll
        for (int e = 0; e < 8; e++)
#pragma unroll
            for (int o = 16; o; o >>= 1) acc[e] += __shfl_xor_sync(~0u, acc[e], o);
        if (lane == 0) {
            int best = 0; float bv = acc[0];
#pragma unroll
            for (int e = 1; e < 8; e++) if (acc[e] > bv) { bv = acc[e]; best = e; }
            g_sel[n] = best;
            atomicAdd(&sHist[best], 1);
        }
    }
    __syncthreads();
    if (tid < 8) g_blockHist[blockIdx.x][tid] = sHist[tid];
}

// ---------------- K2: scan histograms, build tile descriptors ---------------
__global__ void k_scan() {
    __shared__ int sH[128 * 8];
    __shared__ int sOff[128 * 8];
    __shared__ int sCount[8], sPad[8];
    int tid = threadIdx.x;  // 256
    for (int i = tid; i < 1024; i += 256) sH[i] = ((int*)g_blockHist)[i];
    __syncthreads();
    if (tid < 8) {
        int off = 0;
        for (int b = 0; b < 128; b++) { sOff[b * 8 + tid] = off; off += sH[b * 8 + tid]; }
        sCount[tid] = off;
        g_count[tid] = off;
    }
    __syncthreads();
    if (tid == 0) {
        int pb = 0;
        for (int e = 0; e < 8; e++) {
            sPad[e] = pb; g_padBase[e] = pb;
            pb += ((sCount[e] + TILE_T - 1) / TILE_T) * TILE_T;
        }
        int idx = 0;
        for (int e = 0; e < 8; e++) {
            g_tileRange[e] = idx;
            int c = sCount[e];
            for (int i = 0; i * TILE_T < c; i++) {
                g_tileExpert[idx] = e;
                g_tileBase[idx]   = sPad[e] + i * TILE_T;
                g_tileValid[idx]  = min(TILE_T, c - i * TILE_T);
                idx++;
            }
        }
        g_tileRange[8] = idx;
        g_numTiles = idx;
    }
    __syncthreads();
    for (int i = tid; i < 1024; i += 256) {
        int e = i & 7;
        ((int*)g_blockOff)[i] = sPad[e] + sOff[i];
    }
}

// ---------------- K3: stable scatter (deterministic counting sort) ----------
__global__ void k_scatter() {
    __shared__ int sSel[256];
    int tid = threadIdx.x;
    int n = blockIdx.x * 256 + tid;
    int e = g_sel[n];
    sSel[tid] = e;
    __syncthreads();
    int rank = 0;
    for (int i = 0; i < tid; i++) rank += (sSel[i] == e);
    g_perm[g_blockOff[blockIdx.x][e] + rank] = n;
}

// ---------------- K4: score GEMM on HMMA (single-pass fp16) ------------------
// CTA: 128 tokens x 128 hidden, K=1024 in 16 chunks of 64, double-buffered.
#define KC 64
#define SMX 0        // 2 stages x 16KB
#define SMW 32768    // 2 stages x 16KB
#define SMB1 65536
#define SMW2 66048
#define SMRED 66560
#define SMTOK 67584
#define SMTOT 68096

__device__ __forceinline__ void load_chunk(uint32_t smb, const int* sTok,
                                           const char* xB, const char* wB,
                                           int d0, int stage, int tid) {
#pragma unroll
    for (int it = 0; it < 4; it++) {
        int seg = it * 256 + tid;           // 0..1023
        int row = seg >> 3, c16 = seg & 7;  // 16B column block
        uint32_t doff = SW128((uint32_t)(row * 128 + c16 * 16));
        size_t xsrc = (size_t)sTok[row] * (DIM * 2) + d0 * 2 + c16 * 16;
        CPA16(smb + SMX + stage * 16384 + doff, xB + xsrc);
        size_t wsrc = (size_t)row * (DIM * 2) + d0 * 2 + c16 * 16;
        CPA16(smb + SMW + stage * 16384 + doff, wB + wsrc);
    }
    asm volatile("cp.async.commit_group;" ::: "memory");
}

__global__ void __launch_bounds__(256, 1)
k_score(const float* __restrict__ b1, const float* __restrict__ w2) {
    int tile = blockIdx.x;
    if (tile >= g_numTiles) return;
    int nc = blockIdx.y;
    int e = g_tileExpert[tile], tbase = g_tileBase[tile], tvalid = g_tileValid[tile];

    extern __shared__ char sm[];
    uint32_t smb = smem_u32(sm);
    int tid = threadIdx.x, wid = tid >> 5, lane = tid & 31;

    int*   sTok = (int*)(sm + SMTOK);
    float* b1s  = (float*)(sm + SMB1);
    float* w2s  = (float*)(sm + SMW2);
    float* sRed = (float*)(sm + SMRED);

    if (tid < 128) {
        sTok[tid] = g_perm[tbase + min(tid, tvalid - 1)];
        int h = nc * 128 + tid;
        b1s[tid] = b1[e * HID + h];
        w2s[tid] = w2[e * HID + h];
    }
    __syncthreads();

    const char* xB = (const char*)g_xh;
    const char* wB = (const char*)(g_w1h + ((size_t)e * HID + (size_t)nc * 128) * DIM);

    int wm = wid >> 1, wn = wid & 1;
    int m0 = wm * 32, n0 = wn * 64;

    uint32_t aBase = (uint32_t)((m0 + (lane & 15)) * 128 + (lane >> 4) * 16);
    uint32_t bBase = (uint32_t)((n0 + (lane & 7)) * 128 + ((lane >> 3) & 1) * 16);

    float acc[2][8][4];
#pragma unroll
    for (int mt = 0; mt < 2; mt++)
#pragma unroll
        for (int nt = 0; nt < 8; nt++)
#pragma unroll
            for (int j = 0; j < 4; j++) acc[mt][nt][j] = 0.f;

    load_chunk(smb, sTok, xB, wB, 0, 0, tid);

    for (int i = 0; i < 16; i++) {
        int s = i & 1;
        if (i + 1 < 16) {
            load_chunk(smb, sTok, xB, wB, (i + 1) * KC, 1 - s, tid);
            asm volatile("cp.async.wait_group 1;" ::: "memory");
        } else {
            asm volatile("cp.async.wait_group 0;" ::: "memory");
        }
        __syncthreads();

        uint32_t xs = smb + SMX + s * 16384;
        uint32_t ws = smb + SMW + s * 16384;
#pragma unroll
        for (int kk = 0; kk < 4; kk++) {
            uint32_t a[2][4];
#pragma unroll
            for (int mt = 0; mt < 2; mt++)
                LDSM4(a[mt], xs + SW128(aBase + mt * 2048 + kk * 32));
#pragma unroll
            for (int nt = 0; nt < 8; nt++) {
                uint32_t b[2];
                LDSM2(b, ws + SW128(bBase + nt * 1024 + kk * 32));
#pragma unroll
                for (int mt = 0; mt < 2; mt++)
                    MMA_F16(acc[mt][nt], a[mt], b);
            }
        }
        __syncthreads();
    }

    // epilogue: +b1, tanh, dot w2 over this CTA's 128 h-cols
    int g = lane >> 2, qc = lane & 3;
    float rs[4] = {0.f, 0.f, 0.f, 0.f};
#pragma unroll
    for (int mt = 0; mt < 2; mt++)
#pragma unroll
        for (int nt = 0; nt < 8; nt++) {
            int hl = wn * 64 + nt * 8 + qc * 2;
            float w20 = w2s[hl], w21 = w2s[hl + 1];
            float bb0 = b1s[hl], bb1 = b1s[hl + 1];
            rs[mt * 2 + 0] += tanhf(acc[mt][nt][0] + bb0) * w20
                            + tanhf(acc[mt][nt][1] + bb1) * w21;
            rs[mt * 2 + 1] += tanhf(acc[mt][nt][2] + bb0) * w20
                            + tanhf(acc[mt][nt][3] + bb1) * w21;
        }
#pragma unroll
    for (int j = 0; j < 4; j++) {
        rs[j] += __shfl_xor_sync(~0u, rs[j], 1);
        rs[j] += __shfl_xor_sync(~0u, rs[j], 2);
    }
    if (qc == 0) {
        sRed[wn * 128 + m0 + g]      = rs[0];
        sRed[wn * 128 + m0 + g + 8]  = rs[1];
        sRed[wn * 128 + m0 + g + 16] = rs[2];
        sRed[wn * 128 + m0 + g + 24] = rs[3];
    }
    __syncthreads();
    if (tid < 128)
        g_scorePart[((size_t)tile * 4 + nc) * 128 + tid] = sRed[tid] + sRed[128 + tid];
}

// ---------------- K4b: fixed-order reduce of score partials ------------------
__global__ void k_scoreRed(const float* __restrict__ b2) {
    int tile = blockIdx.x;
    if (tile >= g_numTiles) return;
    int t = threadIdx.x;
    float s = b2[g_tileExpert[tile]];
#pragma unroll
    for (int ncc = 0; ncc < 4; ncc++)
        s += g_scorePart[((size_t)tile * 4 + ncc) * 128 + t];
    g_scores[g_tileBase[tile] + t] = s;
}

// ---------------- K5: per-expert softmax stats -------------------------------
__global__ void k_softmax() {
    int e = blockIdx.x;
    int cnt = g_count[e], base = g_padBase[e];
    __shared__ float sred[256];
    int tid = threadIdx.x;
    float m = -3.0e38f;
    for (int i = tid; i < cnt; i += 256) m = fmaxf(m, g_scores[base + i]);
    sred[tid] = m; __syncthreads();
    for (int s = 128; s; s >>= 1) {
        if (tid < s) sred[tid] = fmaxf(sred[tid], sred[tid + s]);
        __syncthreads();
    }
    float mx = sred[0]; __syncthreads();
    float sum = 0.f;
    for (int i = tid; i < cnt; i += 256) sum += expf(g_scores[base + i] - mx);
    sred[tid] = sum; __syncthreads();
    for (int s = 128; s; s >>= 1) {
        if (tid < s) sred[tid] += sred[tid + s];
        __syncthreads();
    }
    if (tid == 0) { g_max[e] = mx; g_sum[e] = (cnt > 0) ? sred[0] : 1.f; }
}

// ---------------- K6: pooled partials ----------------------------------------
__global__ void k_poolA(const float* __restrict__ x) {
    int tile = blockIdx.x;
    if (tile >= g_numTiles) return;
    int e = g_tileExpert[tile], tbase = g_tileBase[tile], tvalid = g_tileValid[tile];
    __shared__ float sWt[TILE_T];
    __shared__ int   sN[TILE_T];
    int tid = threadIdx.x;  // 128
    if (tid < TILE_T) {
        if (tid < tvalid) {
            sWt[tid] = expf(g_scores[tbase + tid] - g_max[e]) / g_sum[e];
            sN[tid]  = g_perm[tbase + tid];
        } else { sWt[tid] = 0.f; sN[tid] = 0; }
    }
    __syncthreads();
    int d = blockIdx.y * 128 + tid;
    float acc = 0.f;
#pragma unroll 4
    for (int t = 0; t < tvalid; t++)
        acc = fmaf(sWt[t], x[(size_t)sN[t] * DIM + d], acc);
    g_partial[(size_t)tile * DIM + d] = acc;
}

// ---------------- K7: fixed-order reduction over tiles -> output -------------
__global__ void k_poolB(float* __restrict__ out) {
    int e = blockIdx.x;
    int d = threadIdx.x;  // 1024
    float acc = 0.f;
    int t0 = g_tileRange[e], t1 = g_tileRange[e + 1];
    for (int t = t0; t < t1; t++)
        acc += g_partial[(size_t)t * DIM + d];
    out[e * DIM + d] = acc;
}

// ---------------- entry ------------------------------------------------------
extern "C" void kernel_launch(void* const* d_in, const int* in_sizes, int n_in,
                              void* d_out, int out_size) {
    const float* x   = (const float*)d_in[0];
    const float* gw  = (const float*)d_in[1];
    const float* W1  = (const float*)d_in[2];
    const float* b1  = (const float*)d_in[3];
    const float* w2  = (const float*)d_in[4];
    const float* b2  = (const float*)d_in[5];
    float* out = (float*)d_out;

    cudaFuncSetAttribute(k_score, cudaFuncAttributeMaxDynamicSharedMemorySize, SMTOT);

    k_cvtW<<<dim3(32, 16, 8), dim3(32, 8)>>>(W1);
    k_gate<<<128, 256>>>(x, gw);
    k_scan<<<1, 256>>>();
    k_scatter<<<128, 256>>>();
    k_score<<<dim3(MAXTILES, 4), 256, SMTOT>>>(b1, w2);
    k_scoreRed<<<MAXTILES, 128>>>(b2);
    k_softmax<<<8, 256>>>();
    k_poolA<<<dim3(MAXTILES, 8), 128>>>(x);
    k_poolB<<<8, 1024>>>(out);
}

// round 6
// speedup vs baseline: 1.0539x; 1.0539x over previous
#include <cuda_runtime.h>
#include <cuda_fp16.h>
#include <cstdint>

#define NTOK 32768
#define DIM  1024
#define HID  512
#define NEXP 8
#define TILE_T 128
#define MAXTILES 264   // 32768/128 + 8

// ---------------- scratch (device globals; no allocations allowed) ----------
__device__ int   g_sel[NTOK];
__device__ int   g_blockHist[128][8];
__device__ int   g_blockOff[128][8];
__device__ int   g_count[8];
__device__ int   g_padBase[8];
__device__ int   g_numTiles;
__device__ int   g_tileExpert[MAXTILES];
__device__ int   g_tileBase[MAXTILES];
__device__ int   g_tileValid[MAXTILES];
__device__ int   g_tileRange[9];
__device__ int   g_perm[NTOK + NEXP * TILE_T];
__device__ float g_scores[NTOK + NEXP * TILE_T];
__device__ float g_scorePart[(size_t)MAXTILES * 4 * 128];
__device__ float g_max[8];
__device__ float g_sum[8];
__device__ float g_partial[(size_t)MAXTILES * DIM];
// inputs converted to fp16 (written by k_gateCvt)
__device__ __half g_xh[(size_t)NTOK * DIM];
// W1 converted to fp16, TRANSPOSED to [E][H][D]
__device__ __half g_w1h[(size_t)NEXP * HID * DIM];

// ---------------- PTX helpers (all sm_80-era; no 'a' features) --------------
__device__ __forceinline__ uint32_t smem_u32(const void* p) {
    uint32_t a;
    asm("{ .reg .u64 t; cvta.to.shared.u64 t, %1; cvt.u32.u64 %0, t; }" : "=r"(a) : "l"(p));
    return a;
}
#define SW128(o) (((uint32_t)(o)) ^ ((((uint32_t)(o)) >> 3) & 0x70))

#define CPA16(dst, src) \
    asm volatile("cp.async.cg.shared.global [%0], [%1], 16;" :: "r"(dst), "l"(src))

#define LDSM4(r, addr) \
    asm volatile("ldmatrix.sync.aligned.m8n8.x4.shared.b16 {%0,%1,%2,%3}, [%4];" \
        : "=r"((r)[0]), "=r"((r)[1]), "=r"((r)[2]), "=r"((r)[3]) : "r"(addr))
#define LDSM2(r, addr) \
    asm volatile("ldmatrix.sync.aligned.m8n8.x2.shared.b16 {%0,%1}, [%2];" \
        : "=r"((r)[0]), "=r"((r)[1]) : "r"(addr))

#define MMA_F16(d, a, b) \
    asm volatile("mma.sync.aligned.m16n8k16.row.col.f32.f16.f16.f32 " \
        "{%0,%1,%2,%3}, {%4,%5,%6,%7}, {%8,%9}, {%0,%1,%2,%3};" \
        : "+f"((d)[0]), "+f"((d)[1]), "+f"((d)[2]), "+f"((d)[3]) \
        : "r"((a)[0]), "r"((a)[1]), "r"((a)[2]), "r"((a)[3]), \
          "r"((b)[0]), "r"((b)[1]))

// ---------------- K1: fused gate (+x->fp16) and W1 convert/transpose --------
__global__ void k_gateCvt(const float* __restrict__ x, const float* __restrict__ gw,
                          const float* __restrict__ W1) {
    if (blockIdx.x < 128) {
        // ---- gate path ----
        __shared__ float sG[NEXP * DIM];
        __shared__ int sHist[8];
        int tid = threadIdx.x;
        if (tid < 8) sHist[tid] = 0;
        float4* sG4 = (float4*)sG;
        const float4* g4 = (const float4*)gw;
#pragma unroll
        for (int i = 0; i < 8; i++) sG4[tid + i * 256] = g4[tid + i * 256];
        __syncthreads();

        int warp = tid >> 5, lane = tid & 31;
        int base = blockIdx.x * 256 + warp * 32;
        for (int it = 0; it < 32; it++) {
            int n = base + it;
            const float* xr = x + (size_t)n * DIM;
            __half* xhr = g_xh + (size_t)n * DIM;
            float acc[8];
#pragma unroll
            for (int e = 0; e < 8; e++) acc[e] = 0.f;
            for (int k = 0; k < 32; k++) {
                int dd = lane + k * 32;
                float xv = xr[dd];
                xhr[dd] = __float2half_rn(xv);
#pragma unroll
                for (int e = 0; e < 8; e++) acc[e] = fmaf(xv, sG[e * DIM + dd], acc[e]);
            }
#pragma unroll
            for (int e = 0; e < 8; e++)
#pragma unroll
                for (int o = 16; o; o >>= 1) acc[e] += __shfl_xor_sync(~0u, acc[e], o);
            if (lane == 0) {
                int best = 0; float bv = acc[0];
#pragma unroll
                for (int e = 1; e < 8; e++) if (acc[e] > bv) { bv = acc[e]; best = e; }
                g_sel[n] = best;
                atomicAdd(&sHist[best], 1);
            }
        }
        __syncthreads();
        if (tid < 8) g_blockHist[blockIdx.x][tid] = sHist[tid];
    } else {
        // ---- W1 convert + transpose path: 4096 32x32 tiles / 128 blocks ----
        __shared__ float t[32][33];
        int bid = blockIdx.x - 128;
        int tx = threadIdx.x & 31, ty = threadIdx.x >> 5;  // 32 x 8
        for (int k = 0; k < 32; k++) {
            int tileId = bid * 32 + k;
            int e  = tileId >> 9;          // 512 tiles per expert (32 d x 16 h)
            int rem = tileId & 511;
            int db = rem >> 4, hb = rem & 15;
            const float* src = W1 + ((size_t)e * DIM + db * 32) * HID + hb * 32;
#pragma unroll
            for (int j = 0; j < 4; j++)
                t[ty + j * 8][tx] = src[(size_t)(ty + j * 8) * HID + tx];
            __syncthreads();
#pragma unroll
            for (int j = 0; j < 4; j++) {
                float v = t[tx][ty + j * 8];
                size_t o = ((size_t)e * HID + hb * 32 + ty + j * 8) * DIM + db * 32 + tx;
                g_w1h[o] = __float2half_rn(v);
            }
            __syncthreads();
        }
    }
}

// ---------------- K2: scan histograms, build tile descriptors ---------------
__global__ void k_scan() {
    __shared__ int sH[128 * 8];
    __shared__ int sOff[128 * 8];
    __shared__ int sCount[8], sPad[8];
    int tid = threadIdx.x;  // 256
    for (int i = tid; i < 1024; i += 256) sH[i] = ((int*)g_blockHist)[i];
    __syncthreads();
    if (tid < 8) {
        int off = 0;
        for (int b = 0; b < 128; b++) { sOff[b * 8 + tid] = off; off += sH[b * 8 + tid]; }
        sCount[tid] = off;
        g_count[tid] = off;
    }
    __syncthreads();
    if (tid == 0) {
        int pb = 0;
        for (int e = 0; e < 8; e++) {
            sPad[e] = pb; g_padBase[e] = pb;
            pb += ((sCount[e] + TILE_T - 1) / TILE_T) * TILE_T;
        }
        int idx = 0;
        for (int e = 0; e < 8; e++) {
            g_tileRange[e] = idx;
            int c = sCount[e];
            for (int i = 0; i * TILE_T < c; i++) {
                g_tileExpert[idx] = e;
                g_tileBase[idx]   = sPad[e] + i * TILE_T;
                g_tileValid[idx]  = min(TILE_T, c - i * TILE_T);
                idx++;
            }
        }
        g_tileRange[8] = idx;
        g_numTiles = idx;
    }
    __syncthreads();
    for (int i = tid; i < 1024; i += 256) {
        int e = i & 7;
        ((int*)g_blockOff)[i] = sPad[e] + sOff[i];
    }
}

// ---------------- K3: stable scatter (deterministic counting sort) ----------
__global__ void k_scatter() {
    __shared__ int sSel[256];
    int tid = threadIdx.x;
    int n = blockIdx.x * 256 + tid;
    int e = g_sel[n];
    sSel[tid] = e;
    __syncthreads();
    int rank = 0;
    for (int i = 0; i < tid; i++) rank += (sSel[i] == e);
    g_perm[g_blockOff[blockIdx.x][e] + rank] = n;
}

// ---------------- K4: score GEMM on HMMA, 3-stage cp.async pipeline ---------
// CTA: 128 tokens x 128 hidden, K=1024 in 16 chunks of 64, triple-buffered.
#define KC 64
#define SMX 0         // 3 stages x 16KB
#define SMW 49152     // 3 stages x 16KB
#define SMB1 98304
#define SMW2 98816
#define SMRED 99328
#define SMTOK 100352
#define SMTOT 100864

__device__ __forceinline__ void load_chunk(uint32_t smb, const int* sTok,
                                           const char* xB, const char* wB,
                                           int d0, int stage, int tid) {
#pragma unroll
    for (int it = 0; it < 4; it++) {
        int seg = it * 256 + tid;           // 0..1023
        int row = seg >> 3, c16 = seg & 7;  // 16B column block
        uint32_t doff = SW128((uint32_t)(row * 128 + c16 * 16));
        size_t xsrc = (size_t)sTok[row] * (DIM * 2) + d0 * 2 + c16 * 16;
        CPA16(smb + SMX + stage * 16384 + doff, xB + xsrc);
        size_t wsrc = (size_t)row * (DIM * 2) + d0 * 2 + c16 * 16;
        CPA16(smb + SMW + stage * 16384 + doff, wB + wsrc);
    }
    asm volatile("cp.async.commit_group;" ::: "memory");
}

__global__ void __launch_bounds__(256, 2)
k_score(const float* __restrict__ b1, const float* __restrict__ w2) {
    int tile = blockIdx.x;
    if (tile >= g_numTiles) return;
    int nc = blockIdx.y;
    int e = g_tileExpert[tile], tbase = g_tileBase[tile], tvalid = g_tileValid[tile];

    extern __shared__ char sm[];
    uint32_t smb = smem_u32(sm);
    int tid = threadIdx.x, wid = tid >> 5, lane = tid & 31;

    int*   sTok = (int*)(sm + SMTOK);
    float* b1s  = (float*)(sm + SMB1);
    float* w2s  = (float*)(sm + SMW2);
    float* sRed = (float*)(sm + SMRED);

    if (tid < 128) {
        sTok[tid] = g_perm[tbase + min(tid, tvalid - 1)];
        int h = nc * 128 + tid;
        b1s[tid] = b1[e * HID + h];
        w2s[tid] = w2[e * HID + h];
    }
    __syncthreads();

    const char* xB = (const char*)g_xh;
    const char* wB = (const char*)(g_w1h + ((size_t)e * HID + (size_t)nc * 128) * DIM);

    int wm = wid >> 1, wn = wid & 1;
    int m0 = wm * 32, n0 = wn * 64;

    uint32_t aBase = (uint32_t)((m0 + (lane & 15)) * 128 + (lane >> 4) * 16);
    uint32_t bBase = (uint32_t)((n0 + (lane & 7)) * 128 + ((lane >> 3) & 1) * 16);

    float acc[2][8][4];
#pragma unroll
    for (int mt = 0; mt < 2; mt++)
#pragma unroll
        for (int nt = 0; nt < 8; nt++)
#pragma unroll
            for (int j = 0; j < 4; j++) acc[mt][nt][j] = 0.f;

    load_chunk(smb, sTok, xB, wB, 0, 0, tid);
    load_chunk(smb, sTok, xB, wB, KC, 1, tid);

    for (int i = 0; i < 16; i++) {
        if (i + 2 < 16) {
            load_chunk(smb, sTok, xB, wB, (i + 2) * KC, (i + 2) % 3, tid);
            asm volatile("cp.async.wait_group 2;" ::: "memory");
        } else if (i + 1 < 16) {
            asm volatile("cp.async.wait_group 1;" ::: "memory");
        } else {
            asm volatile("cp.async.wait_group 0;" ::: "memory");
        }
        __syncthreads();

        uint32_t xs = smb + SMX + (i % 3) * 16384;
        uint32_t ws = smb + SMW + (i % 3) * 16384;
#pragma unroll
        for (int kk = 0; kk < 4; kk++) {
            uint32_t a[2][4];
#pragma unroll
            for (int mt = 0; mt < 2; mt++)
                LDSM4(a[mt], xs + SW128(aBase + mt * 2048 + kk * 32));
#pragma unroll
            for (int nt = 0; nt < 8; nt++) {
                uint32_t b[2];
                LDSM2(b, ws + SW128(bBase + nt * 1024 + kk * 32));
#pragma unroll
                for (int mt = 0; mt < 2; mt++)
                    MMA_F16(acc[mt][nt], a[mt], b);
            }
        }
        __syncthreads();
    }

    // epilogue: +b1, tanh, dot w2 over this CTA's 128 h-cols
    int g = lane >> 2, qc = lane & 3;
    float rs[4] = {0.f, 0.f, 0.f, 0.f};
#pragma unroll
    for (int mt = 0; mt < 2; mt++)
#pragma unroll
        for (int nt = 0; nt < 8; nt++) {
            int hl = wn * 64 + nt * 8 + qc * 2;
            float w20 = w2s[hl], w21 = w2s[hl + 1];
            float bb0 = b1s[hl], bb1 = b1s[hl + 1];
            rs[mt * 2 + 0] += tanhf(acc[mt][nt][0] + bb0) * w20
                            + tanhf(acc[mt][nt][1] + bb1) * w21;
            rs[mt * 2 + 1] += tanhf(acc[mt][nt][2] + bb0) * w20
                            + tanhf(acc[mt][nt][3] + bb1) * w21;
        }
#pragma unroll
    for (int j = 0; j < 4; j++) {
        rs[j] += __shfl_xor_sync(~0u, rs[j], 1);
        rs[j] += __shfl_xor_sync(~0u, rs[j], 2);
    }
    if (qc == 0) {
        sRed[wn * 128 + m0 + g]      = rs[0];
        sRed[wn * 128 + m0 + g + 8]  = rs[1];
        sRed[wn * 128 + m0 + g + 16] = rs[2];
        sRed[wn * 128 + m0 + g + 24] = rs[3];
    }
    __syncthreads();
    if (tid < 128)
        g_scorePart[((size_t)tile * 4 + nc) * 128 + tid] = sRed[tid] + sRed[128 + tid];
}

// ---------------- K4b: fixed-order reduce of score partials ------------------
__global__ void k_scoreRed(const float* __restrict__ b2) {
    int tile = blockIdx.x;
    if (tile >= g_numTiles) return;
    int t = threadIdx.x;
    float s = b2[g_tileExpert[tile]];
#pragma unroll
    for (int ncc = 0; ncc < 4; ncc++)
        s += g_scorePart[((size_t)tile * 4 + ncc) * 128 + t];
    g_scores[g_tileBase[tile] + t] = s;
}

// ---------------- K5: per-expert softmax stats -------------------------------
__global__ void k_softmax() {
    int e = blockIdx.x;
    int cnt = g_count[e], base = g_padBase[e];
    __shared__ float sred[256];
    int tid = threadIdx.x;
    float m = -3.0e38f;
    for (int i = tid; i < cnt; i += 256) m = fmaxf(m, g_scores[base + i]);
    sred[tid] = m; __syncthreads();
    for (int s = 128; s; s >>= 1) {
        if (tid < s) sred[tid] = fmaxf(sred[tid], sred[tid + s]);
        __syncthreads();
    }
    float mx = sred[0]; __syncthreads();
    float sum = 0.f;
    for (int i = tid; i < cnt; i += 256) sum += expf(g_scores[base + i] - mx);
    sred[tid] = sum; __syncthreads();
    for (int s = 128; s; s >>= 1) {
        if (tid < s) sred[tid] += sred[tid + s];
        __syncthreads();
    }
    if (tid == 0) { g_max[e] = mx; g_sum[e] = (cnt > 0) ? sred[0] : 1.f; }
}

// ---------------- K6: pooled partials ----------------------------------------
__global__ void k_poolA(const float* __restrict__ x) {
    int tile = blockIdx.x;
    if (tile >= g_numTiles) return;
    int e = g_tileExpert[tile], tbase = g_tileBase[tile], tvalid = g_tileValid[tile];
    __shared__ float sWt[TILE_T];
    __shared__ int   sN[TILE_T];
    int tid = threadIdx.x;  // 128
    if (tid < TILE_T) {
        if (tid < tvalid) {
            sWt[tid] = expf(g_scores[tbase + tid] - g_max[e]) / g_sum[e];
            sN[tid]  = g_perm[tbase + tid];
        } else { sWt[tid] = 0.f; sN[tid] = 0; }
    }
    __syncthreads();
    int d = blockIdx.y * 128 + tid;
    float acc = 0.f;
#pragma unroll 4
    for (int t = 0; t < tvalid; t++)
        acc = fmaf(sWt[t], x[(size_t)sN[t] * DIM + d], acc);
    g_partial[(size_t)tile * DIM + d] = acc;
}

// ---------------- K7: fixed-order reduction over tiles -> output -------------
__global__ void k_poolB(float* __restrict__ out) {
    int e = blockIdx.x;
    int d = threadIdx.x;  // 1024
    float acc = 0.f;
    int t0 = g_tileRange[e], t1 = g_tileRange[e + 1];
    for (int t = t0; t < t1; t++)
        acc += g_partial[(size_t)t * DIM + d];
    out[e * DIM + d] = acc;
}

// ---------------- entry ------------------------------------------------------
extern "C" void kernel_launch(void* const* d_in, const int* in_sizes, int n_in,
                              void* d_out, int out_size) {
    const float* x   = (const float*)d_in[0];
    const float* gw  = (const float*)d_in[1];
    const float* W1  = (const float*)d_in[2];
    const float* b1  = (const float*)d_in[3];
    const float* w2  = (const float*)d_in[4];
    const float* b2  = (const float*)d_in[5];
    float* out = (float*)d_out;

    cudaFuncSetAttribute(k_score, cudaFuncAttributeMaxDynamicSharedMemorySize, SMTOT);

    k_gateCvt<<<256, 256>>>(x, gw, W1);
    k_scan<<<1, 256>>>();
    k_scatter<<<128, 256>>>();
    k_score<<<dim3(MAXTILES, 4), 256, SMTOT>>>(b1, w2);
    k_scoreRed<<<MAXTILES, 128>>>(b2);
    k_softmax<<<8, 256>>>();
    k_poolA<<<dim3(MAXTILES, 8), 128>>>(x);
    k_poolB<<<8, 1024>>>(out);
}

// round 7
// speedup vs baseline: 1.8123x; 1.7195x over previous
#include <cuda_runtime.h>
#include <cuda_fp16.h>
#include <cstdint>

#define NTOK 32768
#define DIM  1024
#define HID  512
#define NEXP 8
#define TILE_T 128
#define MAXTILES 264   // 32768/128 + 8
#define GB 256         // gate blocks
#define GT 128         // tokens per gate block

// ---------------- scratch (device globals; no allocations allowed) ----------
__device__ int   g_sel[NTOK];
__device__ int   g_blockHist[GB][8];
__device__ int   g_blockOff[GB][8];
__device__ int   g_count[8];
__device__ int   g_padBase[8];
__device__ int   g_numTiles;
__device__ int   g_tileExpert[MAXTILES];
__device__ int   g_tileBase[MAXTILES];
__device__ int   g_tileValid[MAXTILES];
__device__ int   g_tileRange[9];
__device__ int   g_perm[NTOK + NEXP * TILE_T];
__device__ float g_scores[NTOK + NEXP * TILE_T];
__device__ float g_scorePart[(size_t)MAXTILES * 4 * 128];
__device__ float g_max[8];
__device__ float g_sum[8];
__device__ float g_partial[(size_t)MAXTILES * DIM];
// inputs converted to fp16 (written by k_gate)
__device__ __half g_xh[(size_t)NTOK * DIM];
// W1 converted to fp16, TRANSPOSED to [E][H][D]
__device__ __half g_w1h[(size_t)NEXP * HID * DIM];

// ---------------- PTX helpers (all sm_80-era; no 'a' features) --------------
__device__ __forceinline__ uint32_t smem_u32(const void* p) {
    uint32_t a;
    asm("{ .reg .u64 t; cvta.to.shared.u64 t, %1; cvt.u32.u64 %0, t; }" : "=r"(a) : "l"(p));
    return a;
}
#define SW128(o) (((uint32_t)(o)) ^ ((((uint32_t)(o)) >> 3) & 0x70))

#define CPA16(dst, src) \
    asm volatile("cp.async.cg.shared.global [%0], [%1], 16;" :: "r"(dst), "l"(src))

#define LDSM4(r, addr) \
    asm volatile("ldmatrix.sync.aligned.m8n8.x4.shared.b16 {%0,%1,%2,%3}, [%4];" \
        : "=r"((r)[0]), "=r"((r)[1]), "=r"((r)[2]), "=r"((r)[3]) : "r"(addr))
#define LDSM2(r, addr) \
    asm volatile("ldmatrix.sync.aligned.m8n8.x2.shared.b16 {%0,%1}, [%2];" \
        : "=r"((r)[0]), "=r"((r)[1]) : "r"(addr))

#define MMA_F16(d, a, b) \
    asm volatile("mma.sync.aligned.m16n8k16.row.col.f32.f16.f16.f32 " \
        "{%0,%1,%2,%3}, {%4,%5,%6,%7}, {%8,%9}, {%0,%1,%2,%3};" \
        : "+f"((d)[0]), "+f"((d)[1]), "+f"((d)[2]), "+f"((d)[3]) \
        : "r"((a)[0]), "r"((a)[1]), "r"((a)[2]), "r"((a)[3]), \
          "r"((b)[0]), "r"((b)[1]))

// ---------------- K0: convert + transpose W1 to fp16 [E][H][D] ---------------
__global__ void k_cvtW(const float* __restrict__ W1) {
    __shared__ float t[32][33];
    int e = blockIdx.z, db = blockIdx.x, hb = blockIdx.y;
    int tx = threadIdx.x, ty = threadIdx.y;  // 32 x 8
    const float* src = W1 + ((size_t)e * DIM + db * 32) * HID + hb * 32;
#pragma unroll
    for (int j = 0; j < 4; j++)
        t[ty + j * 8][tx] = src[(size_t)(ty + j * 8) * HID + tx];
    __syncthreads();
#pragma unroll
    for (int j = 0; j < 4; j++) {
        float v = t[tx][ty + j * 8];
        size_t o = ((size_t)e * HID + hb * 32 + ty + j * 8) * DIM + db * 32 + tx;
        g_w1h[o] = __float2half_rn(v);
    }
}

// ---------------- K1: gate + argmax + histogram + x->fp16 (vectorized) ------
__global__ void __launch_bounds__(256)
k_gate(const float* __restrict__ x, const float* __restrict__ gw) {
    __shared__ float4 sG4[NEXP * 256];   // 32 KB gate weights
    __shared__ int sHist[8];
    int tid = threadIdx.x;
    if (tid < 8) sHist[tid] = 0;
    const float4* g4 = (const float4*)gw;
#pragma unroll
    for (int i = 0; i < 8; i++) sG4[tid + i * 256] = g4[tid + i * 256];
    __syncthreads();

    int warp = tid >> 5, lane = tid & 31;
    int base = blockIdx.x * GT + warp * (GT / 8);
    for (int it = 0; it < GT / 8; it++) {
        int n = base + it;
        const float4* xr4 = (const float4*)(x + (size_t)n * DIM);
        uint2* xhr = (uint2*)(g_xh + (size_t)n * DIM);

        float4 v[8];
#pragma unroll
        for (int j = 0; j < 8; j++) v[j] = xr4[j * 32 + lane];   // 8 indep LDG.128

#pragma unroll
        for (int j = 0; j < 8; j++) {                            // fused x->fp16
            __half2 h0 = __floats2half2_rn(v[j].x, v[j].y);
            __half2 h1 = __floats2half2_rn(v[j].z, v[j].w);
            xhr[j * 32 + lane] = make_uint2(*(uint32_t*)&h0, *(uint32_t*)&h1);
        }

        float acc[8];
#pragma unroll
        for (int e = 0; e < 8; e++) acc[e] = 0.f;
#pragma unroll
        for (int j = 0; j < 8; j++)
#pragma unroll
            for (int e = 0; e < 8; e++) {
                float4 g = sG4[e * 256 + j * 32 + lane];
                acc[e] += v[j].x * g.x + v[j].y * g.y + v[j].z * g.z + v[j].w * g.w;
            }
#pragma unroll
        for (int e = 0; e < 8; e++)
#pragma unroll
            for (int o = 16; o; o >>= 1) acc[e] += __shfl_xor_sync(~0u, acc[e], o);
        if (lane == 0) {
            int best = 0; float bv = acc[0];
#pragma unroll
            for (int e = 1; e < 8; e++) if (acc[e] > bv) { bv = acc[e]; best = e; }
            g_sel[n] = best;
            atomicAdd(&sHist[best], 1);
        }
    }
    __syncthreads();
    if (tid < 8) g_blockHist[blockIdx.x][tid] = sHist[tid];
}

// ---------------- K2: scan histograms, build tile descriptors ---------------
__global__ void k_scan() {
    __shared__ int sH[GB * 8];
    __shared__ int sOff[GB * 8];
    __shared__ int sCount[8], sPad[8];
    int tid = threadIdx.x;  // 256
    for (int i = tid; i < GB * 8; i += 256) sH[i] = ((int*)g_blockHist)[i];
    __syncthreads();
    if (tid < 8) {
        int off = 0;
        for (int b = 0; b < GB; b++) { sOff[b * 8 + tid] = off; off += sH[b * 8 + tid]; }
        sCount[tid] = off;
        g_count[tid] = off;
    }
    __syncthreads();
    if (tid == 0) {
        int pb = 0;
        for (int e = 0; e < 8; e++) {
            sPad[e] = pb; g_padBase[e] = pb;
            pb += ((sCount[e] + TILE_T - 1) / TILE_T) * TILE_T;
        }
        int idx = 0;
        for (int e = 0; e < 8; e++) {
            g_tileRange[e] = idx;
            int c = sCount[e];
            for (int i = 0; i * TILE_T < c; i++) {
                g_tileExpert[idx] = e;
                g_tileBase[idx]   = sPad[e] + i * TILE_T;
                g_tileValid[idx]  = min(TILE_T, c - i * TILE_T);
                idx++;
            }
        }
        g_tileRange[8] = idx;
        g_numTiles = idx;
    }
    __syncthreads();
    for (int i = tid; i < GB * 8; i += 256) {
        int e = i & 7;
        ((int*)g_blockOff)[i] = sPad[e] + sOff[i];
    }
}

// ---------------- K3: stable scatter (deterministic counting sort) ----------
__global__ void k_scatter() {
    __shared__ int sSel[GT];
    int tid = threadIdx.x;  // 128
    int n = blockIdx.x * GT + tid;
    int e = g_sel[n];
    sSel[tid] = e;
    __syncthreads();
    int rank = 0;
    for (int i = 0; i < tid; i++) rank += (sSel[i] == e);
    g_perm[g_blockOff[blockIdx.x][e] + rank] = n;
}

// ---------------- K4: score GEMM on HMMA, 3-stage cp.async pipeline ---------
#define KC 64
#define SMX 0         // 3 stages x 16KB
#define SMW 49152     // 3 stages x 16KB
#define SMB1 98304
#define SMW2 98816
#define SMRED 99328
#define SMTOK 100352
#define SMTOT 100864

__device__ __forceinline__ void load_chunk(uint32_t smb, const int* sTok,
                                           const char* xB, const char* wB,
                                           int d0, int stage, int tid) {
#pragma unroll
    for (int it = 0; it < 4; it++) {
        int seg = it * 256 + tid;           // 0..1023
        int row = seg >> 3, c16 = seg & 7;  // 16B column block
        uint32_t doff = SW128((uint32_t)(row * 128 + c16 * 16));
        size_t xsrc = (size_t)sTok[row] * (DIM * 2) + d0 * 2 + c16 * 16;
        CPA16(smb + SMX + stage * 16384 + doff, xB + xsrc);
        size_t wsrc = (size_t)row * (DIM * 2) + d0 * 2 + c16 * 16;
        CPA16(smb + SMW + stage * 16384 + doff, wB + wsrc);
    }
    asm volatile("cp.async.commit_group;" ::: "memory");
}

__global__ void __launch_bounds__(256, 2)
k_score(const float* __restrict__ b1, const float* __restrict__ w2) {
    int tile = blockIdx.x;
    if (tile >= g_numTiles) return;
    int nc = blockIdx.y;
    int e = g_tileExpert[tile], tbase = g_tileBase[tile], tvalid = g_tileValid[tile];

    extern __shared__ char sm[];
    uint32_t smb = smem_u32(sm);
    int tid = threadIdx.x, wid = tid >> 5, lane = tid & 31;

    int*   sTok = (int*)(sm + SMTOK);
    float* b1s  = (float*)(sm + SMB1);
    float* w2s  = (float*)(sm + SMW2);
    float* sRed = (float*)(sm + SMRED);

    if (tid < 128) {
        sTok[tid] = g_perm[tbase + min(tid, tvalid - 1)];
        int h = nc * 128 + tid;
        b1s[tid] = b1[e * HID + h];
        w2s[tid] = w2[e * HID + h];
    }
    __syncthreads();

    const char* xB = (const char*)g_xh;
    const char* wB = (const char*)(g_w1h + ((size_t)e * HID + (size_t)nc * 128) * DIM);

    int wm = wid >> 1, wn = wid & 1;
    int m0 = wm * 32, n0 = wn * 64;

    uint32_t aBase = (uint32_t)((m0 + (lane & 15)) * 128 + (lane >> 4) * 16);
    uint32_t bBase = (uint32_t)((n0 + (lane & 7)) * 128 + ((lane >> 3) & 1) * 16);

    float acc[2][8][4];
#pragma unroll
    for (int mt = 0; mt < 2; mt++)
#pragma unroll
        for (int nt = 0; nt < 8; nt++)
#pragma unroll
            for (int j = 0; j < 4; j++) acc[mt][nt][j] = 0.f;

    load_chunk(smb, sTok, xB, wB, 0, 0, tid);
    load_chunk(smb, sTok, xB, wB, KC, 1, tid);

    for (int i = 0; i < 16; i++) {
        if (i + 2 < 16) {
            load_chunk(smb, sTok, xB, wB, (i + 2) * KC, (i + 2) % 3, tid);
            asm volatile("cp.async.wait_group 2;" ::: "memory");
        } else if (i + 1 < 16) {
            asm volatile("cp.async.wait_group 1;" ::: "memory");
        } else {
            asm volatile("cp.async.wait_group 0;" ::: "memory");
        }
        __syncthreads();

        uint32_t xs = smb + SMX + (i % 3) * 16384;
        uint32_t ws = smb + SMW + (i % 3) * 16384;
#pragma unroll
        for (int kk = 0; kk < 4; kk++) {
            uint32_t a[2][4];
#pragma unroll
            for (int mt = 0; mt < 2; mt++)
                LDSM4(a[mt], xs + SW128(aBase + mt * 2048 + kk * 32));
#pragma unroll
            for (int nt = 0; nt < 8; nt++) {
                uint32_t b[2];
                LDSM2(b, ws + SW128(bBase + nt * 1024 + kk * 32));
#pragma unroll
                for (int mt = 0; mt < 2; mt++)
                    MMA_F16(acc[mt][nt], a[mt], b);
            }
        }
        __syncthreads();
    }

    // epilogue: +b1, tanh, dot w2 over this CTA's 128 h-cols
    int g = lane >> 2, qc = lane & 3;
    float rs[4] = {0.f, 0.f, 0.f, 0.f};
#pragma unroll
    for (int mt = 0; mt < 2; mt++)
#pragma unroll
        for (int nt = 0; nt < 8; nt++) {
            int hl = wn * 64 + nt * 8 + qc * 2;
            float w20 = w2s[hl], w21 = w2s[hl + 1];
            float bb0 = b1s[hl], bb1 = b1s[hl + 1];
            rs[mt * 2 + 0] += tanhf(acc[mt][nt][0] + bb0) * w20
                            + tanhf(acc[mt][nt][1] + bb1) * w21;
            rs[mt * 2 + 1] += tanhf(acc[mt][nt][2] + bb0) * w20
                            + tanhf(acc[mt][nt][3] + bb1) * w21;
        }
#pragma unroll
    for (int j = 0; j < 4; j++) {
        rs[j] += __shfl_xor_sync(~0u, rs[j], 1);
        rs[j] += __shfl_xor_sync(~0u, rs[j], 2);
    }
    if (qc == 0) {
        sRed[wn * 128 + m0 + g]      = rs[0];
        sRed[wn * 128 + m0 + g + 8]  = rs[1];
        sRed[wn * 128 + m0 + g + 16] = rs[2];
        sRed[wn * 128 + m0 + g + 24] = rs[3];
    }
    __syncthreads();
    if (tid < 128)
        g_scorePart[((size_t)tile * 4 + nc) * 128 + tid] = sRed[tid] + sRed[128 + tid];
}

// ---------------- K4b: fixed-order reduce of score partials ------------------
__global__ void k_scoreRed(const float* __restrict__ b2) {
    int tile = blockIdx.x;
    if (tile >= g_numTiles) return;
    int t = threadIdx.x;
    float s = b2[g_tileExpert[tile]];
#pragma unroll
    for (int ncc = 0; ncc < 4; ncc++)
        s += g_scorePart[((size_t)tile * 4 + ncc) * 128 + t];
    g_scores[g_tileBase[tile] + t] = s;
}

// ---------------- K5: per-expert softmax stats -------------------------------
__global__ void k_softmax() {
    int e = blockIdx.x;
    int cnt = g_count[e], base = g_padBase[e];
    __shared__ float sred[256];
    int tid = threadIdx.x;
    float m = -3.0e38f;
    for (int i = tid; i < cnt; i += 256) m = fmaxf(m, g_scores[base + i]);
    sred[tid] = m; __syncthreads();
    for (int s = 128; s; s >>= 1) {
        if (tid < s) sred[tid] = fmaxf(sred[tid], sred[tid + s]);
        __syncthreads();
    }
    float mx = sred[0]; __syncthreads();
    float sum = 0.f;
    for (int i = tid; i < cnt; i += 256) sum += expf(g_scores[base + i] - mx);
    sred[tid] = sum; __syncthreads();
    for (int s = 128; s; s >>= 1) {
        if (tid < s) sred[tid] += sred[tid + s];
        __syncthreads();
    }
    if (tid == 0) { g_max[e] = mx; g_sum[e] = (cnt > 0) ? sred[0] : 1.f; }
}

// ---------------- K6: pooled partials ----------------------------------------
__global__ void k_poolA(const float* __restrict__ x) {
    int tile = blockIdx.x;
    if (tile >= g_numTiles) return;
    int e = g_tileExpert[tile], tbase = g_tileBase[tile], tvalid = g_tileValid[tile];
    __shared__ float sWt[TILE_T];
    __shared__ int   sN[TILE_T];
    int tid = threadIdx.x;  // 128
    if (tid < TILE_T) {
        if (tid < tvalid) {
            sWt[tid] = expf(g_scores[tbase + tid] - g_max[e]) / g_sum[e];
            sN[tid]  = g_perm[tbase + tid];
        } else { sWt[tid] = 0.f; sN[tid] = 0; }
    }
    __syncthreads();
    int d = blockIdx.y * 128 + tid;
    float acc = 0.f;
#pragma unroll 8
    for (int t = 0; t < tvalid; t++)
        acc = fmaf(sWt[t], x[(size_t)sN[t] * DIM + d], acc);
    g_partial[(size_t)tile * DIM + d] = acc;
}

// ---------------- K7: fixed-order reduction over tiles -> output -------------
__global__ void k_poolB(float* __restrict__ out) {
    int e = blockIdx.x;
    int d = threadIdx.x;  // 1024
    float acc = 0.f;
    int t0 = g_tileRange[e], t1 = g_tileRange[e + 1];
    for (int t = t0; t < t1; t++)
        acc += g_partial[(size_t)t * DIM + d];
    out[e * DIM + d] = acc;
}

// ---------------- entry ------------------------------------------------------
extern "C" void kernel_launch(void* const* d_in, const int* in_sizes, int n_in,
                              void* d_out, int out_size) {
    const float* x   = (const float*)d_in[0];
    const float* gw  = (const float*)d_in[1];
    const float* W1  = (const float*)d_in[2];
    const float* b1  = (const float*)d_in[3];
    const float* w2  = (const float*)d_in[4];
    const float* b2  = (const float*)d_in[5];
    float* out = (float*)d_out;

    cudaFuncSetAttribute(k_score, cudaFuncAttributeMaxDynamicSharedMemorySize, SMTOT);

    k_cvtW<<<dim3(32, 16, 8), dim3(32, 8)>>>(W1);
    k_gate<<<GB, 256>>>(x, gw);
    k_scan<<<1, 256>>>();
    k_scatter<<<GB, GT>>>();
    k_score<<<dim3(MAXTILES, 4), 256, SMTOT>>>(b1, w2);
    k_scoreRed<<<MAXTILES, 128>>>(b2);
    k_softmax<<<8, 256>>>();
    k_poolA<<<dim3(MAXTILES, 8), 128>>>(x);
    k_poolB<<<8, 1024>>>(out);
}

// round 8
// speedup vs baseline: 1.8910x; 1.0435x over previous
#include <cuda_runtime.h>
#include <cuda_fp16.h>
#include <cstdint>

#define NTOK 32768
#define DIM  1024
#define HID  512
#define NEXP 8
#define TILE_T 128
#define MAXTILES 264   // 32768/128 + 8
#define GB 256         // gate blocks
#define GT 128         // tokens per gate block

// ---------------- scratch (device globals; no allocations allowed) ----------
__device__ int   g_sel[NTOK];
__device__ int   g_blockHist[GB][8];
__device__ int   g_blockOff[GB][8];
__device__ int   g_count[8];
__device__ int   g_padBase[8];
__device__ int   g_numTiles;
__device__ int   g_tileExpert[MAXTILES];
__device__ int   g_tileBase[MAXTILES];
__device__ int   g_tileValid[MAXTILES];
__device__ int   g_tileRange[9];
__device__ int   g_perm[NTOK + NEXP * TILE_T];
__device__ float g_scores[NTOK + NEXP * TILE_T];
__device__ float g_scorePart[(size_t)MAXTILES * 4 * 128];
__device__ float g_max[8];
__device__ float g_sum[8];
__device__ float g_partial[(size_t)MAXTILES * DIM];
__device__ __half g_xh[(size_t)NTOK * DIM];
__device__ __half g_w1h[(size_t)NEXP * HID * DIM];

// ---------------- PTX helpers (all sm_80-era; no 'a' features) --------------
__device__ __forceinline__ uint32_t smem_u32(const void* p) {
    uint32_t a;
    asm("{ .reg .u64 t; cvta.to.shared.u64 t, %1; cvt.u32.u64 %0, t; }" : "=r"(a) : "l"(p));
    return a;
}
#define SW128(o) (((uint32_t)(o)) ^ ((((uint32_t)(o)) >> 3) & 0x70))

#define CPA16(dst, src) \
    asm volatile("cp.async.cg.shared.global [%0], [%1], 16;" :: "r"(dst), "l"(src))

#define LDSM4(r, addr) \
    asm volatile("ldmatrix.sync.aligned.m8n8.x4.shared.b16 {%0,%1,%2,%3}, [%4];" \
        : "=r"((r)[0]), "=r"((r)[1]), "=r"((r)[2]), "=r"((r)[3]) : "r"(addr))

#define MMA_F16(d, a, b) \
    asm volatile("mma.sync.aligned.m16n8k16.row.col.f32.f16.f16.f32 " \
        "{%0,%1,%2,%3}, {%4,%5,%6,%7}, {%8,%9}, {%0,%1,%2,%3};" \
        : "+f"((d)[0]), "+f"((d)[1]), "+f"((d)[2]), "+f"((d)[3]) \
        : "r"((a)[0]), "r"((a)[1]), "r"((a)[2]), "r"((a)[3]), \
          "r"((b)[0]), "r"((b)[1]))

// ---------------- K1: fused gate (+x->fp16) and W1 convert/transpose --------
__global__ void __launch_bounds__(256)
k_gateCvt(const float* __restrict__ x, const float* __restrict__ gw,
          const float* __restrict__ W1) {
    if (blockIdx.x < GB) {
        // ---- vectorized gate path ----
        __shared__ float4 sG4[NEXP * 256];   // 32 KB
        __shared__ int sHist[8];
        int tid = threadIdx.x;
        if (tid < 8) sHist[tid] = 0;
        const float4* g4 = (const float4*)gw;
#pragma unroll
        for (int i = 0; i < 8; i++) sG4[tid + i * 256] = g4[tid + i * 256];
        __syncthreads();

        int warp = tid >> 5, lane = tid & 31;
        int base = blockIdx.x * GT + warp * (GT / 8);
        for (int it = 0; it < GT / 8; it++) {
            int n = base + it;
            const float4* xr4 = (const float4*)(x + (size_t)n * DIM);
            uint2* xhr = (uint2*)(g_xh + (size_t)n * DIM);

            float4 v[8];
#pragma unroll
            for (int j = 0; j < 8; j++) v[j] = xr4[j * 32 + lane];
#pragma unroll
            for (int j = 0; j < 8; j++) {
                __half2 h0 = __floats2half2_rn(v[j].x, v[j].y);
                __half2 h1 = __floats2half2_rn(v[j].z, v[j].w);
                xhr[j * 32 + lane] = make_uint2(*(uint32_t*)&h0, *(uint32_t*)&h1);
            }
            float acc[8];
#pragma unroll
            for (int e = 0; e < 8; e++) acc[e] = 0.f;
#pragma unroll
            for (int j = 0; j < 8; j++)
#pragma unroll
                for (int e = 0; e < 8; e++) {
                    float4 g = sG4[e * 256 + j * 32 + lane];
                    acc[e] += v[j].x * g.x + v[j].y * g.y + v[j].z * g.z + v[j].w * g.w;
                }
#pragma unroll
            for (int e = 0; e < 8; e++)
#pragma unroll
                for (int o = 16; o; o >>= 1) acc[e] += __shfl_xor_sync(~0u, acc[e], o);
            if (lane == 0) {
                int best = 0; float bv = acc[0];
#pragma unroll
                for (int e = 1; e < 8; e++) if (acc[e] > bv) { bv = acc[e]; best = e; }
                g_sel[n] = best;
                atomicAdd(&sHist[best], 1);
            }
        }
        __syncthreads();
        if (tid < 8) g_blockHist[blockIdx.x][tid] = sHist[tid];
    } else {
        // ---- W1 convert + transpose: 4096 32x32 tiles / 128 blocks ----
        __shared__ float t[32][33];
        int bid = blockIdx.x - GB;
        int tx = threadIdx.x & 31, ty = threadIdx.x >> 5;  // 32 x 8
        for (int k = 0; k < 32; k++) {
            int tileId = bid * 32 + k;
            int e  = tileId >> 9;
            int rem = tileId & 511;
            int db = rem >> 4, hb = rem & 15;
            const float* src = W1 + ((size_t)e * DIM + db * 32) * HID + hb * 32;
#pragma unroll
            for (int j = 0; j < 4; j++)
                t[ty + j * 8][tx] = src[(size_t)(ty + j * 8) * HID + tx];
            __syncthreads();
#pragma unroll
            for (int j = 0; j < 4; j++) {
                float v = t[tx][ty + j * 8];
                size_t o = ((size_t)e * HID + hb * 32 + ty + j * 8) * DIM + db * 32 + tx;
                g_w1h[o] = __float2half_rn(v);
            }
            __syncthreads();
        }
    }
}

// ---------------- K2: scan histograms, build tile descriptors ---------------
__global__ void k_scan() {
    __shared__ int sH[GB * 8];
    __shared__ int sOff[GB * 8];
    __shared__ int sCount[8], sPad[8];
    int tid = threadIdx.x;  // 256
    for (int i = tid; i < GB * 8; i += 256) sH[i] = ((int*)g_blockHist)[i];
    __syncthreads();
    if (tid < 8) {
        int off = 0;
        for (int b = 0; b < GB; b++) { sOff[b * 8 + tid] = off; off += sH[b * 8 + tid]; }
        sCount[tid] = off;
        g_count[tid] = off;
    }
    __syncthreads();
    if (tid == 0) {
        int pb = 0;
        for (int e = 0; e < 8; e++) {
            sPad[e] = pb; g_padBase[e] = pb;
            pb += ((sCount[e] + TILE_T - 1) / TILE_T) * TILE_T;
        }
        int idx = 0;
        for (int e = 0; e < 8; e++) {
            g_tileRange[e] = idx;
            int c = sCount[e];
            for (int i = 0; i * TILE_T < c; i++) {
                g_tileExpert[idx] = e;
                g_tileBase[idx]   = sPad[e] + i * TILE_T;
                g_tileValid[idx]  = min(TILE_T, c - i * TILE_T);
                idx++;
            }
        }
        g_tileRange[8] = idx;
        g_numTiles = idx;
    }
    __syncthreads();
    for (int i = tid; i < GB * 8; i += 256) {
        int e = i & 7;
        ((int*)g_blockOff)[i] = sPad[e] + sOff[i];
    }
}

// ---------------- K3: stable scatter (deterministic counting sort) ----------
__global__ void k_scatter() {
    __shared__ int sSel[GT];
    int tid = threadIdx.x;  // 128
    int n = blockIdx.x * GT + tid;
    int e = g_sel[n];
    sSel[tid] = e;
    __syncthreads();
    int rank = 0;
    for (int i = 0; i < tid; i++) rank += (sSel[i] == e);
    g_perm[g_blockOff[blockIdx.x][e] + rank] = n;
}

// ---------------- K4: score GEMM on HMMA, 3-stage cp.async pipeline ---------
#define KC 64
#define SMX 0         // 3 stages x 16KB
#define SMW 49152     // 3 stages x 16KB
#define SMB1 98304
#define SMW2 98816
#define SMRED 99328
#define SMTOK 100352
#define SMTOT 100864

__device__ __forceinline__ void load_chunk(uint32_t smb, const int* sTok,
                                           const char* xB, const char* wB,
                                           int d0, int stage, int tid) {
#pragma unroll
    for (int it = 0; it < 4; it++) {
        int seg = it * 256 + tid;           // 0..1023
        int row = seg >> 3, c16 = seg & 7;  // 16B column block
        uint32_t doff = SW128((uint32_t)(row * 128 + c16 * 16));
        size_t xsrc = (size_t)sTok[row] * (DIM * 2) + d0 * 2 + c16 * 16;
        CPA16(smb + SMX + stage * 16384 + doff, xB + xsrc);
        size_t wsrc = (size_t)row * (DIM * 2) + d0 * 2 + c16 * 16;
        CPA16(smb + SMW + stage * 16384 + doff, wB + wsrc);
    }
    asm volatile("cp.async.commit_group;" ::: "memory");
}

__global__ void __launch_bounds__(256, 2)
k_score(const float* __restrict__ b1, const float* __restrict__ w2) {
    int tile = blockIdx.x;
    if (tile >= g_numTiles) return;
    int nc = blockIdx.y;
    int e = g_tileExpert[tile], tbase = g_tileBase[tile], tvalid = g_tileValid[tile];

    extern __shared__ char sm[];
    uint32_t smb = smem_u32(sm);
    int tid = threadIdx.x, wid = tid >> 5, lane = tid & 31;

    int*   sTok = (int*)(sm + SMTOK);
    float* b1s  = (float*)(sm + SMB1);
    float* w2s  = (float*)(sm + SMW2);
    float* sRed = (float*)(sm + SMRED);

    if (tid < 128) {
        sTok[tid] = g_perm[tbase + min(tid, tvalid - 1)];
        int h = nc * 128 + tid;
        b1s[tid] = b1[e * HID + h];
        w2s[tid] = w2[e * HID + h];
    }
    __syncthreads();

    const char* xB = (const char*)g_xh;
    const char* wB = (const char*)(g_w1h + ((size_t)e * HID + (size_t)nc * 128) * DIM);

    int wm = wid >> 1, wn = wid & 1;
    int m0 = wm * 32, n0 = wn * 64;

    uint32_t aBase  = (uint32_t)((m0 + (lane & 15)) * 128 + (lane >> 4) * 16);
    // x4 B: lanes 0-7 -> n rows 0-7 khalf0, 8-15 -> rows 0-7 khalf1,
    //       16-23 -> rows 8-15 khalf0, 24-31 -> rows 8-15 khalf1
    uint32_t bBase4 = (uint32_t)((n0 + (lane >> 4) * 8 + (lane & 7)) * 128 +
                                 ((lane >> 3) & 1) * 16);

    float acc[2][8][4];
#pragma unroll
    for (int mt = 0; mt < 2; mt++)
#pragma unroll
        for (int nt = 0; nt < 8; nt++)
#pragma unroll
            for (int j = 0; j < 4; j++) acc[mt][nt][j] = 0.f;

    load_chunk(smb, sTok, xB, wB, 0, 0, tid);
    load_chunk(smb, sTok, xB, wB, KC, 1, tid);

    for (int i = 0; i < 16; i++) {
        if (i + 2 < 16) {
            load_chunk(smb, sTok, xB, wB, (i + 2) * KC, (i + 2) % 3, tid);
            asm volatile("cp.async.wait_group 2;" ::: "memory");
        } else if (i + 1 < 16) {
            asm volatile("cp.async.wait_group 1;" ::: "memory");
        } else {
            asm volatile("cp.async.wait_group 0;" ::: "memory");
        }
        __syncthreads();

        uint32_t xs = smb + SMX + (i % 3) * 16384;
        uint32_t ws = smb + SMW + (i % 3) * 16384;
#pragma unroll
        for (int kk = 0; kk < 4; kk++) {
            uint32_t a[2][4];
#pragma unroll
            for (int mt = 0; mt < 2; mt++)
                LDSM4(a[mt], xs + SW128(aBase + mt * 2048 + kk * 32));
#pragma unroll
            for (int nt2 = 0; nt2 < 4; nt2++) {
                uint32_t b4[4];
                LDSM4(b4, ws + SW128(bBase4 + nt2 * 2048 + kk * 32));
#pragma unroll
                for (int mt = 0; mt < 2; mt++) {
                    MMA_F16(acc[mt][nt2 * 2],     a[mt], b4);
                    MMA_F16(acc[mt][nt2 * 2 + 1], a[mt], b4 + 2);
                }
            }
        }
        __syncthreads();
    }

    // epilogue: +b1, tanh, dot w2 over this CTA's 128 h-cols
    int g = lane >> 2, qc = lane & 3;
    float rs[4] = {0.f, 0.f, 0.f, 0.f};
#pragma unroll
    for (int mt = 0; mt < 2; mt++)
#pragma unroll
        for (int nt = 0; nt < 8; nt++) {
            int hl = wn * 64 + nt * 8 + qc * 2;
            float w20 = w2s[hl], w21 = w2s[hl + 1];
            float bb0 = b1s[hl], bb1 = b1s[hl + 1];
            rs[mt * 2 + 0] += tanhf(acc[mt][nt][0] + bb0) * w20
                            + tanhf(acc[mt][nt][1] + bb1) * w21;
            rs[mt * 2 + 1] += tanhf(acc[mt][nt][2] + bb0) * w20
                            + tanhf(acc[mt][nt][3] + bb1) * w21;
        }
#pragma unroll
    for (int j = 0; j < 4; j++) {
        rs[j] += __shfl_xor_sync(~0u, rs[j], 1);
        rs[j] += __shfl_xor_sync(~0u, rs[j], 2);
    }
    if (qc == 0) {
        sRed[wn * 128 + m0 + g]      = rs[0];
        sRed[wn * 128 + m0 + g + 8]  = rs[1];
        sRed[wn * 128 + m0 + g + 16] = rs[2];
        sRed[wn * 128 + m0 + g + 24] = rs[3];
    }
    __syncthreads();
    if (tid < 128)
        g_scorePart[((size_t)tile * 4 + nc) * 128 + tid] = sRed[tid] + sRed[128 + tid];
}

// ---------------- K5: fused scoreRed + per-expert softmax stats --------------
__global__ void k_softmax(const float* __restrict__ b2) {
    int e = blockIdx.x;
    int cnt = g_count[e], base = g_padBase[e];
    int tile0 = g_tileRange[e];
    float b2e = b2[e];
    __shared__ float sred[256];
    int tid = threadIdx.x;
    float m = -3.0e38f;
    for (int i = tid; i < cnt; i += 256) {
        size_t tb = ((size_t)(tile0 + (i >> 7)) * 4) * 128 + (i & 127);
        float s = b2e + g_scorePart[tb] + g_scorePart[tb + 128]
                + g_scorePart[tb + 256] + g_scorePart[tb + 384];
        g_scores[base + i] = s;
        m = fmaxf(m, s);
    }
    sred[tid] = m; __syncthreads();
    for (int s = 128; s; s >>= 1) {
        if (tid < s) sred[tid] = fmaxf(sred[tid], sred[tid + s]);
        __syncthreads();
    }
    float mx = sred[0]; __syncthreads();
    float sum = 0.f;
    for (int i = tid; i < cnt; i += 256) sum += expf(g_scores[base + i] - mx);
    sred[tid] = sum; __syncthreads();
    for (int s = 128; s; s >>= 1) {
        if (tid < s) sred[tid] += sred[tid + s];
        __syncthreads();
    }
    if (tid == 0) { g_max[e] = mx; g_sum[e] = (cnt > 0) ? sred[0] : 1.f; }
}

// ---------------- K6: pooled partials ----------------------------------------
__global__ void k_poolA(const float* __restrict__ x) {
    int tile = blockIdx.x;
    if (tile >= g_numTiles) return;
    int e = g_tileExpert[tile], tbase = g_tileBase[tile], tvalid = g_tileValid[tile];
    __shared__ float sWt[TILE_T];
    __shared__ int   sN[TILE_T];
    int tid = threadIdx.x;  // 128
    if (tid < TILE_T) {
        if (tid < tvalid) {
            sWt[tid] = expf(g_scores[tbase + tid] - g_max[e]) / g_sum[e];
            sN[tid]  = g_perm[tbase + tid];
        } else { sWt[tid] = 0.f; sN[tid] = 0; }
    }
    __syncthreads();
    int d = blockIdx.y * 128 + tid;
    float acc = 0.f;
#pragma unroll 8
    for (int t = 0; t < tvalid; t++)
        acc = fmaf(sWt[t], x[(size_t)sN[t] * DIM + d], acc);
    g_partial[(size_t)tile * DIM + d] = acc;
}

// ---------------- K7: fixed-order reduction over tiles -> output -------------
__global__ void k_poolB(float* __restrict__ out) {
    int e = blockIdx.x;
    int d = threadIdx.x;  // 1024
    float acc = 0.f;
    int t0 = g_tileRange[e], t1 = g_tileRange[e + 1];
    for (int t = t0; t < t1; t++)
        acc += g_partial[(size_t)t * DIM + d];
    out[e * DIM + d] = acc;
}

// ---------------- entry ------------------------------------------------------
extern "C" void kernel_launch(void* const* d_in, const int* in_sizes, int n_in,
                              void* d_out, int out_size) {
    const float* x   = (const float*)d_in[0];
    const float* gw  = (const float*)d_in[1];
    const float* W1  = (const float*)d_in[2];
    const float* b1  = (const float*)d_in[3];
    const float* w2  = (const float*)d_in[4];
    const float* b2  = (const float*)d_in[5];
    float* out = (float*)d_out;

    cudaFuncSetAttribute(k_score, cudaFuncAttributeMaxDynamicSharedMemorySize, SMTOT);

    k_gateCvt<<<GB + 128, 256>>>(x, gw, W1);
    k_scan<<<1, 256>>>();
    k_scatter<<<GB, GT>>>();
    k_score<<<dim3(MAXTILES, 4), 256, SMTOT>>>(b1, w2);
    k_softmax<<<8, 256>>>(b2);
    k_poolA<<<dim3(MAXTILES, 8), 128>>>(x);
    k_poolB<<<8, 1024>>>(out);
}

// round 9
// speedup vs baseline: 2.0341x; 1.0757x over previous
#include <cuda_runtime.h>
#include <cuda_fp16.h>
#include <cstdint>

#define NTOK 32768
#define DIM  1024
#define HID  512
#define NEXP 8
#define TILE_T 128
#define MAXTILES 264   // 32768/128 + 8
#define GB 256         // gate blocks
#define GT 128         // tokens per gate block

// ---------------- scratch (device globals; no allocations allowed) ----------
__device__ int   g_sel[NTOK];
__device__ int   g_blockHist[GB][8];
__device__ int   g_blockOff[GB][8];
__device__ int   g_count[8];
__device__ int   g_numTiles;
__device__ int   g_tileExpert[MAXTILES];
__device__ int   g_tileBase[MAXTILES];
__device__ int   g_tileValid[MAXTILES];
__device__ int   g_tileRange[9];
__device__ int   g_perm[NTOK + NEXP * TILE_T];
__device__ float g_scorePart[(size_t)MAXTILES * 4 * 128];
__device__ float g_wtsum[MAXTILES];
__device__ float g_partial[(size_t)MAXTILES * DIM];
__device__ __half g_xh[(size_t)NTOK * DIM];
__device__ __half g_w1h[(size_t)NEXP * HID * DIM];

// ---------------- PTX helpers (all sm_80-era; no 'a' features) --------------
__device__ __forceinline__ uint32_t smem_u32(const void* p) {
    uint32_t a;
    asm("{ .reg .u64 t; cvta.to.shared.u64 t, %1; cvt.u32.u64 %0, t; }" : "=r"(a) : "l"(p));
    return a;
}
#define SW128(o) (((uint32_t)(o)) ^ ((((uint32_t)(o)) >> 3) & 0x70))

#define CPA16(dst, src) \
    asm volatile("cp.async.cg.shared.global [%0], [%1], 16;" :: "r"(dst), "l"(src))

#define LDSM4(r, addr) \
    asm volatile("ldmatrix.sync.aligned.m8n8.x4.shared.b16 {%0,%1,%2,%3}, [%4];" \
        : "=r"((r)[0]), "=r"((r)[1]), "=r"((r)[2]), "=r"((r)[3]) : "r"(addr))

#define MMA_F16(d, a, b) \
    asm volatile("mma.sync.aligned.m16n8k16.row.col.f32.f16.f16.f32 " \
        "{%0,%1,%2,%3}, {%4,%5,%6,%7}, {%8,%9}, {%0,%1,%2,%3};" \
        : "+f"((d)[0]), "+f"((d)[1]), "+f"((d)[2]), "+f"((d)[3]) \
        : "r"((a)[0]), "r"((a)[1]), "r"((a)[2]), "r"((a)[3]), \
          "r"((b)[0]), "r"((b)[1]))

// ---------------- K1: fused gate (+x->fp16) and W1 convert/transpose --------
__global__ void __launch_bounds__(256)
k_gateCvt(const float* __restrict__ x, const float* __restrict__ gw,
          const float* __restrict__ W1) {
    if (blockIdx.x < GB) {
        __shared__ float4 sG4[NEXP * 256];   // 32 KB
        __shared__ int sHist[8];
        int tid = threadIdx.x;
        if (tid < 8) sHist[tid] = 0;
        const float4* g4 = (const float4*)gw;
#pragma unroll
        for (int i = 0; i < 8; i++) sG4[tid + i * 256] = g4[tid + i * 256];
        __syncthreads();

        int warp = tid >> 5, lane = tid & 31;
        int base = blockIdx.x * GT + warp * (GT / 8);
        for (int it = 0; it < GT / 8; it++) {
            int n = base + it;
            const float4* xr4 = (const float4*)(x + (size_t)n * DIM);
            uint2* xhr = (uint2*)(g_xh + (size_t)n * DIM);

            float4 v[8];
#pragma unroll
            for (int j = 0; j < 8; j++) v[j] = xr4[j * 32 + lane];
#pragma unroll
            for (int j = 0; j < 8; j++) {
                __half2 h0 = __floats2half2_rn(v[j].x, v[j].y);
                __half2 h1 = __floats2half2_rn(v[j].z, v[j].w);
                xhr[j * 32 + lane] = make_uint2(*(uint32_t*)&h0, *(uint32_t*)&h1);
            }
            float acc[8];
#pragma unroll
            for (int e = 0; e < 8; e++) acc[e] = 0.f;
#pragma unroll
            for (int j = 0; j < 8; j++)
#pragma unroll
                for (int e = 0; e < 8; e++) {
                    float4 g = sG4[e * 256 + j * 32 + lane];
                    acc[e] += v[j].x * g.x + v[j].y * g.y + v[j].z * g.z + v[j].w * g.w;
                }
#pragma unroll
            for (int e = 0; e < 8; e++)
#pragma unroll
                for (int o = 16; o; o >>= 1) acc[e] += __shfl_xor_sync(~0u, acc[e], o);
            if (lane == 0) {
                int best = 0; float bv = acc[0];
#pragma unroll
                for (int e = 1; e < 8; e++) if (acc[e] > bv) { bv = acc[e]; best = e; }
                g_sel[n] = best;
                atomicAdd(&sHist[best], 1);
            }
        }
        __syncthreads();
        if (tid < 8) g_blockHist[blockIdx.x][tid] = sHist[tid];
    } else {
        // ---- W1 convert + transpose: 4096 32x32 tiles / 128 blocks ----
        __shared__ float t[32][33];
        int bid = blockIdx.x - GB;
        int tx = threadIdx.x & 31, ty = threadIdx.x >> 5;  // 32 x 8
        for (int k = 0; k < 32; k++) {
            int tileId = bid * 32 + k;
            int e  = tileId >> 9;
            int rem = tileId & 511;
            int db = rem >> 4, hb = rem & 15;
            const float* src = W1 + ((size_t)e * DIM + db * 32) * HID + hb * 32;
#pragma unroll
            for (int j = 0; j < 4; j++)
                t[ty + j * 8][tx] = src[(size_t)(ty + j * 8) * HID + tx];
            __syncthreads();
#pragma unroll
            for (int j = 0; j < 4; j++) {
                float v = t[tx][ty + j * 8];
                size_t o = ((size_t)e * HID + hb * 32 + ty + j * 8) * DIM + db * 32 + tx;
                g_w1h[o] = __float2half_rn(v);
            }
            __syncthreads();
        }
    }
}

// ---------------- K2: scan histograms (warp-parallel), build tiles ----------
__global__ void k_scan() {
    __shared__ int sOff[GB * 8];
    __shared__ int sCount[8], sPad[8];
    int tid = threadIdx.x;  // 256
    int warp = tid >> 5, lane = tid & 31;
    // warp e scans expert e's 256 block-counts
    if (warp < 8) {
        int v[8], pre[8];
        int tot = 0;
#pragma unroll
        for (int j = 0; j < 8; j++) {
            v[j] = g_blockHist[lane * 8 + j][warp];
            pre[j] = tot;
            tot += v[j];
        }
        int excl = 0, run = tot;
#pragma unroll
        for (int o = 1; o < 32; o <<= 1) {
            int up = __shfl_up_sync(~0u, run, o);
            if (lane >= o) excl += up;
            run += (lane >= o) ? up : 0;
            run = excl + tot;    // keep run = inclusive-prefix for next step
        }
#pragma unroll
        for (int j = 0; j < 8; j++)
            sOff[(lane * 8 + j) * 8 + warp] = excl + pre[j];
        if (lane == 31) sCount[warp] = excl + tot;
    }
    __syncthreads();
    if (tid == 0) {
        int pb = 0;
        for (int e = 0; e < 8; e++) {
            sPad[e] = pb;
            g_count[e] = sCount[e];
            pb += ((sCount[e] + TILE_T - 1) / TILE_T) * TILE_T;
        }
        int idx = 0;
        for (int e = 0; e < 8; e++) {
            g_tileRange[e] = idx;
            int c = sCount[e];
            for (int i = 0; i * TILE_T < c; i++) {
                g_tileExpert[idx] = e;
                g_tileBase[idx]   = sPad[e] + i * TILE_T;
                g_tileValid[idx]  = min(TILE_T, c - i * TILE_T);
                idx++;
            }
        }
        g_tileRange[8] = idx;
        g_numTiles = idx;
    }
    __syncthreads();
    for (int i = tid; i < GB * 8; i += 256) {
        int e = i & 7;
        ((int*)g_blockOff)[i] = sPad[e] + sOff[i];
    }
}

// ---------------- K3: stable scatter (deterministic counting sort) ----------
__global__ void k_scatter() {
    __shared__ int sSel[GT];
    int tid = threadIdx.x;  // 128
    int n = blockIdx.x * GT + tid;
    int e = g_sel[n];
    sSel[tid] = e;
    __syncthreads();
    int rank = 0;
    for (int i = 0; i < tid; i++) rank += (sSel[i] == e);
    g_perm[g_blockOff[blockIdx.x][e] + rank] = n;
}

// ---------------- K4: score GEMM on HMMA, 3-stage cp.async pipeline ---------
#define KC 64
#define SMX 0         // 3 stages x 16KB
#define SMW 49152     // 3 stages x 16KB
#define SMB1 98304
#define SMW2 98816
#define SMRED 99328
#define SMTOK 100352
#define SMTOT 100864

__device__ __forceinline__ void load_chunk(uint32_t smb, const int* sTok,
                                           const char* xB, const char* wB,
                                           int d0, int stage, int tid) {
#pragma unroll
    for (int it = 0; it < 4; it++) {
        int seg = it * 256 + tid;           // 0..1023
        int row = seg >> 3, c16 = seg & 7;  // 16B column block
        uint32_t doff = SW128((uint32_t)(row * 128 + c16 * 16));
        size_t xsrc = (size_t)sTok[row] * (DIM * 2) + d0 * 2 + c16 * 16;
        CPA16(smb + SMX + stage * 16384 + doff, xB + xsrc);
        size_t wsrc = (size_t)row * (DIM * 2) + d0 * 2 + c16 * 16;
        CPA16(smb + SMW + stage * 16384 + doff, wB + wsrc);
    }
    asm volatile("cp.async.commit_group;" ::: "memory");
}

__global__ void __launch_bounds__(256, 2)
k_score(const float* __restrict__ b1, const float* __restrict__ w2) {
    int tile = blockIdx.x;
    if (tile >= g_numTiles) return;
    int nc = blockIdx.y;
    int e = g_tileExpert[tile], tbase = g_tileBase[tile], tvalid = g_tileValid[tile];

    extern __shared__ char sm[];
    uint32_t smb = smem_u32(sm);
    int tid = threadIdx.x, wid = tid >> 5, lane = tid & 31;

    int*   sTok = (int*)(sm + SMTOK);
    float* b1s  = (float*)(sm + SMB1);
    float* w2s  = (float*)(sm + SMW2);
    float* sRed = (float*)(sm + SMRED);

    if (tid < 128) {
        sTok[tid] = g_perm[tbase + min(tid, tvalid - 1)];
        int h = nc * 128 + tid;
        b1s[tid] = b1[e * HID + h];
        w2s[tid] = w2[e * HID + h];
    }
    __syncthreads();

    const char* xB = (const char*)g_xh;
    const char* wB = (const char*)(g_w1h + ((size_t)e * HID + (size_t)nc * 128) * DIM);

    int wm = wid >> 1, wn = wid & 1;
    int m0 = wm * 32, n0 = wn * 64;

    uint32_t aBase  = (uint32_t)((m0 + (lane & 15)) * 128 + (lane >> 4) * 16);
    uint32_t bBase4 = (uint32_t)((n0 + (lane >> 4) * 8 + (lane & 7)) * 128 +
                                 ((lane >> 3) & 1) * 16);

    float acc[2][8][4];
#pragma unroll
    for (int mt = 0; mt < 2; mt++)
#pragma unroll
        for (int nt = 0; nt < 8; nt++)
#pragma unroll
            for (int j = 0; j < 4; j++) acc[mt][nt][j] = 0.f;

    load_chunk(smb, sTok, xB, wB, 0, 0, tid);
    load_chunk(smb, sTok, xB, wB, KC, 1, tid);

    for (int i = 0; i < 16; i++) {
        if (i + 2 < 16) {
            load_chunk(smb, sTok, xB, wB, (i + 2) * KC, (i + 2) % 3, tid);
            asm volatile("cp.async.wait_group 2;" ::: "memory");
        } else if (i + 1 < 16) {
            asm volatile("cp.async.wait_group 1;" ::: "memory");
        } else {
            asm volatile("cp.async.wait_group 0;" ::: "memory");
        }
        __syncthreads();

        uint32_t xs = smb + SMX + (i % 3) * 16384;
        uint32_t ws = smb + SMW + (i % 3) * 16384;
#pragma unroll
        for (int kk = 0; kk < 4; kk++) {
            uint32_t a[2][4];
#pragma unroll
            for (int mt = 0; mt < 2; mt++)
                LDSM4(a[mt], xs + SW128(aBase + mt * 2048 + kk * 32));
#pragma unroll
            for (int nt2 = 0; nt2 < 4; nt2++) {
                uint32_t b4[4];
                LDSM4(b4, ws + SW128(bBase4 + nt2 * 2048 + kk * 32));
#pragma unroll
                for (int mt = 0; mt < 2; mt++) {
                    MMA_F16(acc[mt][nt2 * 2],     a[mt], b4);
                    MMA_F16(acc[mt][nt2 * 2 + 1], a[mt], b4 + 2);
                }
            }
        }
        __syncthreads();
    }

    // epilogue: +b1, tanh, dot w2 over this CTA's 128 h-cols
    int g = lane >> 2, qc = lane & 3;
    float rs[4] = {0.f, 0.f, 0.f, 0.f};
#pragma unroll
    for (int mt = 0; mt < 2; mt++)
#pragma unroll
        for (int nt = 0; nt < 8; nt++) {
            int hl = wn * 64 + nt * 8 + qc * 2;
            float w20 = w2s[hl], w21 = w2s[hl + 1];
            float bb0 = b1s[hl], bb1 = b1s[hl + 1];
            rs[mt * 2 + 0] += tanhf(acc[mt][nt][0] + bb0) * w20
                            + tanhf(acc[mt][nt][1] + bb1) * w21;
            rs[mt * 2 + 1] += tanhf(acc[mt][nt][2] + bb0) * w20
                            + tanhf(acc[mt][nt][3] + bb1) * w21;
        }
#pragma unroll
    for (int j = 0; j < 4; j++) {
        rs[j] += __shfl_xor_sync(~0u, rs[j], 1);
        rs[j] += __shfl_xor_sync(~0u, rs[j], 2);
    }
    if (qc == 0) {
        sRed[wn * 128 + m0 + g]      = rs[0];
        sRed[wn * 128 + m0 + g + 8]  = rs[1];
        sRed[wn * 128 + m0 + g + 16] = rs[2];
        sRed[wn * 128 + m0 + g + 24] = rs[3];
    }
    __syncthreads();
    if (tid < 128)
        g_scorePart[((size_t)tile * 4 + nc) * 128 + tid] = sRed[tid] + sRed[128 + tid];
}

// ---------------- K6: pooled partials, softmax-free (raw exp weights) --------
__global__ void k_poolA(const float* __restrict__ b2) {
    int tile = blockIdx.x;
    if (tile >= g_numTiles) return;
    int e = g_tileExpert[tile], tbase = g_tileBase[tile], tvalid = g_tileValid[tile];
    __shared__ float sWt[TILE_T];
    __shared__ int   sN[TILE_T];
    __shared__ float sSum[4];
    int tid = threadIdx.x;  // 128
    {
        float wt = 0.f;
        if (tid < tvalid) {
            size_t tb = ((size_t)tile * 4) * 128 + tid;
            float s = b2[e] + g_scorePart[tb] + g_scorePart[tb + 128]
                    + g_scorePart[tb + 256] + g_scorePart[tb + 384];
            wt = expf(s);      // |s| small; no max-subtraction needed
            sN[tid] = g_perm[tbase + tid];
        } else sN[tid] = 0;
        sWt[tid] = wt;
        if (blockIdx.y == 0) {   // per-tile weight sum (deterministic tree)
            float v = wt;
#pragma unroll
            for (int o = 16; o; o >>= 1) v += __shfl_xor_sync(~0u, v, o);
            if ((tid & 31) == 0) sSum[tid >> 5] = v;
        }
    }
    __syncthreads();
    if (blockIdx.y == 0 && tid == 0)
        g_wtsum[tile] = (sSum[0] + sSum[1]) + (sSum[2] + sSum[3]);

    int dh = blockIdx.y * 128 + tid;  // half2 index: 256 floats per y-block
    float2 acc = make_float2(0.f, 0.f);
#pragma unroll 8
    for (int t = 0; t < tvalid; t++) {
        __half2 hv = ((const __half2*)(g_xh + (size_t)sN[t] * DIM))[dh];
        float2 fv = __half22float2(hv);
        float w = sWt[t];
        acc.x = fmaf(w, fv.x, acc.x);
        acc.y = fmaf(w, fv.y, acc.y);
    }
    ((float2*)g_partial)[(size_t)tile * (DIM / 2) + dh] = acc;
}

// ---------------- K7: fixed-order reduce + normalize -> output ---------------
__global__ void k_poolB(float* __restrict__ out) {
    int e = blockIdx.x;
    int d = threadIdx.x;  // 1024
    int t0 = g_tileRange[e], t1 = g_tileRange[e + 1];
    float acc = 0.f, wsum = 0.f;
    for (int t = t0; t < t1; t++) {
        acc  += g_partial[(size_t)t * DIM + d];
        wsum += g_wtsum[t];
    }
    out[e * DIM + d] = (wsum > 0.f) ? acc / wsum : 0.f;
}

// ---------------- entry ------------------------------------------------------
extern "C" void kernel_launch(void* const* d_in, const int* in_sizes, int n_in,
                              void* d_out, int out_size) {
    const float* x   = (const float*)d_in[0];
    const float* gw  = (const float*)d_in[1];
    const float* W1  = (const float*)d_in[2];
    const float* b1  = (const float*)d_in[3];
    const float* w2  = (const float*)d_in[4];
    const float* b2  = (const float*)d_in[5];
    float* out = (float*)d_out;

    cudaFuncSetAttribute(k_score, cudaFuncAttributeMaxDynamicSharedMemorySize, SMTOT);

    k_gateCvt<<<GB + 128, 256>>>(x, gw, W1);
    k_scan<<<1, 256>>>();
    k_scatter<<<GB, GT>>>();
    k_score<<<dim3(MAXTILES, 4), 256, SMTOT>>>(b1, w2);
    k_poolA<<<dim3(MAXTILES, 4), 128>>>(b2);
    k_poolB<<<8, 1024>>>(out);
}

// round 10
// speedup vs baseline: 2.1192x; 1.0418x over previous
#include <cuda_runtime.h>
#include <cuda_fp16.h>
#include <cstdint>

#define NTOK 32768
#define DIM  1024
#define HID  512
#define NEXP 8
#define TILE_T 128
#define MAXTILES 264   // 32768/128 + 8
#define GB 256         // gate blocks
#define GT 128         // tokens per gate block

// ---------------- scratch (device globals; no allocations allowed) ----------
__device__ int   g_sel[NTOK];
__device__ int   g_blockHist[GB][8];
__device__ int   g_count[8];
__device__ int   g_perm[NTOK + NEXP * TILE_T];
__device__ float g_scorePart[(size_t)MAXTILES * 4 * 128];
__device__ float g_wtsum[MAXTILES];
__device__ float g_partial[(size_t)MAXTILES * DIM];
__device__ __half g_xh[(size_t)NTOK * DIM];
__device__ __half g_w1h[(size_t)NEXP * HID * DIM];

// ---------------- PTX helpers (all sm_80-era; no 'a' features) --------------
__device__ __forceinline__ uint32_t smem_u32(const void* p) {
    uint32_t a;
    asm("{ .reg .u64 t; cvta.to.shared.u64 t, %1; cvt.u32.u64 %0, t; }" : "=r"(a) : "l"(p));
    return a;
}
#define SW128(o) (((uint32_t)(o)) ^ ((((uint32_t)(o)) >> 3) & 0x70))

#define CPA16(dst, src) \
    asm volatile("cp.async.cg.shared.global [%0], [%1], 16;" :: "r"(dst), "l"(src))

#define LDSM4(r, addr) \
    asm volatile("ldmatrix.sync.aligned.m8n8.x4.shared.b16 {%0,%1,%2,%3}, [%4];" \
        : "=r"((r)[0]), "=r"((r)[1]), "=r"((r)[2]), "=r"((r)[3]) : "r"(addr))

#define MMA_F16(d, a, b) \
    asm volatile("mma.sync.aligned.m16n8k16.row.col.f32.f16.f16.f32 " \
        "{%0,%1,%2,%3}, {%4,%5,%6,%7}, {%8,%9}, {%0,%1,%2,%3};" \
        : "+f"((d)[0]), "+f"((d)[1]), "+f"((d)[2]), "+f"((d)[3]) \
        : "r"((a)[0]), "r"((a)[1]), "r"((a)[2]), "r"((a)[3]), \
          "r"((b)[0]), "r"((b)[1]))

// ---------------- inline tile descriptor from g_count ------------------------
struct TInfo { int e, tbase, tvalid, ntiles; };
__device__ __forceinline__ TInfo tile_info(int tile) {
    TInfo r; r.e = -1; r.tbase = 0; r.tvalid = 0;
    int idx = 0, pad = 0;
#pragma unroll
    for (int k = 0; k < 8; k++) {
        int c = g_count[k];
        int t = (c + TILE_T - 1) >> 7;
        if (r.e < 0 && tile < idx + t) {
            int li = tile - idx;
            r.e = k;
            r.tbase = pad + (li << 7);
            r.tvalid = min(TILE_T, c - (li << 7));
        }
        idx += t; pad += t << 7;
    }
    r.ntiles = idx;
    if (r.e < 0) r.e = 0;
    return r;
}

// ---------------- K1: fused gate (+x->fp16) and W1 convert/transpose --------
__global__ void __launch_bounds__(256)
k_gateCvt(const float* __restrict__ x, const float* __restrict__ gw,
          const float* __restrict__ W1) {
    if (blockIdx.x < GB) {
        __shared__ float4 sG4[NEXP * 256];   // 32 KB
        __shared__ int sHist[8];
        int tid = threadIdx.x;
        if (tid < 8) sHist[tid] = 0;
        const float4* g4 = (const float4*)gw;
#pragma unroll
        for (int i = 0; i < 8; i++) sG4[tid + i * 256] = g4[tid + i * 256];
        __syncthreads();

        int warp = tid >> 5, lane = tid & 31;
        int base = blockIdx.x * GT + warp * (GT / 8);
        for (int it = 0; it < GT / 8; it++) {
            int n = base + it;
            const float4* xr4 = (const float4*)(x + (size_t)n * DIM);
            uint2* xhr = (uint2*)(g_xh + (size_t)n * DIM);

            float4 v[8];
#pragma unroll
            for (int j = 0; j < 8; j++) v[j] = xr4[j * 32 + lane];
#pragma unroll
            for (int j = 0; j < 8; j++) {
                __half2 h0 = __floats2half2_rn(v[j].x, v[j].y);
                __half2 h1 = __floats2half2_rn(v[j].z, v[j].w);
                xhr[j * 32 + lane] = make_uint2(*(uint32_t*)&h0, *(uint32_t*)&h1);
            }
            float acc[8];
#pragma unroll
            for (int e = 0; e < 8; e++) acc[e] = 0.f;
#pragma unroll
            for (int j = 0; j < 8; j++)
#pragma unroll
                for (int e = 0; e < 8; e++) {
                    float4 g = sG4[e * 256 + j * 32 + lane];
                    acc[e] += v[j].x * g.x + v[j].y * g.y + v[j].z * g.z + v[j].w * g.w;
                }
#pragma unroll
            for (int e = 0; e < 8; e++)
#pragma unroll
                for (int o = 16; o; o >>= 1) acc[e] += __shfl_xor_sync(~0u, acc[e], o);
            if (lane == 0) {
                int best = 0; float bv = acc[0];
#pragma unroll
                for (int e = 1; e < 8; e++) if (acc[e] > bv) { bv = acc[e]; best = e; }
                g_sel[n] = best;
                atomicAdd(&sHist[best], 1);
            }
        }
        __syncthreads();
        if (tid < 8) g_blockHist[blockIdx.x][tid] = sHist[tid];
    } else {
        // ---- W1 convert + transpose: 4096 32x32 tiles / 128 blocks ----
        __shared__ float t[32][33];
        int bid = blockIdx.x - GB;
        int tx = threadIdx.x & 31, ty = threadIdx.x >> 5;  // 32 x 8
        for (int k = 0; k < 32; k++) {
            int tileId = bid * 32 + k;
            int e  = tileId >> 9;
            int rem = tileId & 511;
            int db = rem >> 4, hb = rem & 15;
            const float* src = W1 + ((size_t)e * DIM + db * 32) * HID + hb * 32;
#pragma unroll
            for (int j = 0; j < 4; j++)
                t[ty + j * 8][tx] = src[(size_t)(ty + j * 8) * HID + tx];
            __syncthreads();
#pragma unroll
            for (int j = 0; j < 4; j++) {
                float v = t[tx][ty + j * 8];
                size_t o = ((size_t)e * HID + hb * 32 + ty + j * 8) * DIM + db * 32 + tx;
                g_w1h[o] = __float2half_rn(v);
            }
            __syncthreads();
        }
    }
}

// ---------------- K3: scatter with per-block local scan (k_scan deleted) ----
__global__ void __launch_bounds__(256)
k_scatter() {
    __shared__ int sSel[GT];
    __shared__ int sCnt[8], sPre[8], sOffE[8];
    int tid = threadIdx.x, warp = tid >> 5, lane = tid & 31;
    int b = blockIdx.x;

    if (tid < GT) sSel[tid] = g_sel[b * GT + tid];

    // warp e: total count of expert e, and prefix over blocks < b
    {
        int tot = 0, pre = 0;
#pragma unroll
        for (int j = 0; j < 8; j++) {
            int bb = lane + j * 32;
            int h = g_blockHist[bb][warp];
            tot += h;
            pre += (bb < b) ? h : 0;
        }
#pragma unroll
        for (int o = 16; o; o >>= 1) {
            tot += __shfl_xor_sync(~0u, tot, o);
            pre += __shfl_xor_sync(~0u, pre, o);
        }
        if (lane == 0) { sCnt[warp] = tot; sPre[warp] = pre; }
    }
    __syncthreads();
    if (tid == 0) {
        int pad = 0;
#pragma unroll
        for (int e = 0; e < 8; e++) {
            sOffE[e] = pad + sPre[e];
            if (b == 0) g_count[e] = sCnt[e];
            pad += ((sCnt[e] + TILE_T - 1) >> 7) << 7;
        }
    }
    __syncthreads();
    if (tid < GT) {
        int e = sSel[tid];
        int rank = 0;
        for (int i = 0; i < tid; i++) rank += (sSel[i] == e);
        g_perm[sOffE[e] + rank] = b * GT + tid;
    }
}

// ---------------- K4: score GEMM on HMMA, 3-stage cp.async pipeline ---------
#define KC 64
#define SMX 0         // 3 stages x 16KB
#define SMW 49152     // 3 stages x 16KB
#define SMB1 98304
#define SMW2 98816
#define SMRED 99328
#define SMTOK 100352
#define SMTOT 100864

__device__ __forceinline__ void load_chunk(uint32_t smb, const int* sTok,
                                           const char* xB, const char* wB,
                                           int d0, int stage, int tid) {
#pragma unroll
    for (int it = 0; it < 4; it++) {
        int seg = it * 256 + tid;           // 0..1023
        int row = seg >> 3, c16 = seg & 7;  // 16B column block
        uint32_t doff = SW128((uint32_t)(row * 128 + c16 * 16));
        size_t xsrc = (size_t)sTok[row] * (DIM * 2) + d0 * 2 + c16 * 16;
        CPA16(smb + SMX + stage * 16384 + doff, xB + xsrc);
        size_t wsrc = (size_t)row * (DIM * 2) + d0 * 2 + c16 * 16;
        CPA16(smb + SMW + stage * 16384 + doff, wB + wsrc);
    }
    asm volatile("cp.async.commit_group;" ::: "memory");
}

__global__ void __launch_bounds__(256, 2)
k_score(const float* __restrict__ b1, const float* __restrict__ w2) {
    int tile = blockIdx.x;
    TInfo ti = tile_info(tile);
    if (tile >= ti.ntiles) return;
    int nc = blockIdx.y;
    int e = ti.e, tbase = ti.tbase, tvalid = ti.tvalid;

    extern __shared__ char sm[];
    uint32_t smb = smem_u32(sm);
    int tid = threadIdx.x, wid = tid >> 5, lane = tid & 31;

    int*   sTok = (int*)(sm + SMTOK);
    float* b1s  = (float*)(sm + SMB1);
    float* w2s  = (float*)(sm + SMW2);
    float* sRed = (float*)(sm + SMRED);

    if (tid < 128) {
        sTok[tid] = g_perm[tbase + min(tid, tvalid - 1)];
        int h = nc * 128 + tid;
        b1s[tid] = b1[e * HID + h];
        w2s[tid] = w2[e * HID + h];
    }
    __syncthreads();

    const char* xB = (const char*)g_xh;
    const char* wB = (const char*)(g_w1h + ((size_t)e * HID + (size_t)nc * 128) * DIM);

    int wm = wid >> 1, wn = wid & 1;
    int m0 = wm * 32, n0 = wn * 64;

    uint32_t aBase  = (uint32_t)((m0 + (lane & 15)) * 128 + (lane >> 4) * 16);
    uint32_t bBase4 = (uint32_t)((n0 + (lane >> 4) * 8 + (lane & 7)) * 128 +
                                 ((lane >> 3) & 1) * 16);

    float acc[2][8][4];
#pragma unroll
    for (int mt = 0; mt < 2; mt++)
#pragma unroll
        for (int nt = 0; nt < 8; nt++)
#pragma unroll
            for (int j = 0; j < 4; j++) acc[mt][nt][j] = 0.f;

    load_chunk(smb, sTok, xB, wB, 0, 0, tid);
    load_chunk(smb, sTok, xB, wB, KC, 1, tid);

    for (int i = 0; i < 16; i++) {
        if (i + 2 < 16) {
            load_chunk(smb, sTok, xB, wB, (i + 2) * KC, (i + 2) % 3, tid);
            asm volatile("cp.async.wait_group 2;" ::: "memory");
        } else if (i + 1 < 16) {
            asm volatile("cp.async.wait_group 1;" ::: "memory");
        } else {
            asm volatile("cp.async.wait_group 0;" ::: "memory");
        }
        __syncthreads();

        uint32_t xs = smb + SMX + (i % 3) * 16384;
        uint32_t ws = smb + SMW + (i % 3) * 16384;
#pragma unroll
        for (int kk = 0; kk < 4; kk++) {
            uint32_t a[2][4];
#pragma unroll
            for (int mt = 0; mt < 2; mt++)
                LDSM4(a[mt], xs + SW128(aBase + mt * 2048 + kk * 32));
#pragma unroll
            for (int nt2 = 0; nt2 < 4; nt2++) {
                uint32_t b4[4];
                LDSM4(b4, ws + SW128(bBase4 + nt2 * 2048 + kk * 32));
#pragma unroll
                for (int mt = 0; mt < 2; mt++) {
                    MMA_F16(acc[mt][nt2 * 2],     a[mt], b4);
                    MMA_F16(acc[mt][nt2 * 2 + 1], a[mt], b4 + 2);
                }
            }
        }
        __syncthreads();
    }

    // epilogue: +b1, tanh, dot w2 over this CTA's 128 h-cols
    int g = lane >> 2, qc = lane & 3;
    float rs[4] = {0.f, 0.f, 0.f, 0.f};
#pragma unroll
    for (int mt = 0; mt < 2; mt++)
#pragma unroll
        for (int nt = 0; nt < 8; nt++) {
            int hl = wn * 64 + nt * 8 + qc * 2;
            float w20 = w2s[hl], w21 = w2s[hl + 1];
            float bb0 = b1s[hl], bb1 = b1s[hl + 1];
            rs[mt * 2 + 0] += tanhf(acc[mt][nt][0] + bb0) * w20
                            + tanhf(acc[mt][nt][1] + bb1) * w21;
            rs[mt * 2 + 1] += tanhf(acc[mt][nt][2] + bb0) * w20
                            + tanhf(acc[mt][nt][3] + bb1) * w21;
        }
#pragma unroll
    for (int j = 0; j < 4; j++) {
        rs[j] += __shfl_xor_sync(~0u, rs[j], 1);
        rs[j] += __shfl_xor_sync(~0u, rs[j], 2);
    }
    if (qc == 0) {
        sRed[wn * 128 + m0 + g]      = rs[0];
        sRed[wn * 128 + m0 + g + 8]  = rs[1];
        sRed[wn * 128 + m0 + g + 16] = rs[2];
        sRed[wn * 128 + m0 + g + 24] = rs[3];
    }
    __syncthreads();
    if (tid < 128)
        g_scorePart[((size_t)tile * 4 + nc) * 128 + tid] = sRed[tid] + sRed[128 + tid];
}

// ---------------- K6: pooled partials, softmax-free (raw exp weights) --------
__global__ void __launch_bounds__(128)
k_poolA(const float* __restrict__ b2) {
    int tile = blockIdx.x;
    TInfo ti = tile_info(tile);
    if (tile >= ti.ntiles) return;
    int e = ti.e, tbase = ti.tbase, tvalid = ti.tvalid;
    __shared__ float sWt[TILE_T];
    __shared__ int   sN[TILE_T];
    __shared__ float sSum[4];
    int tid = threadIdx.x;  // 128
    {
        float wt = 0.f;
        if (tid < tvalid) {
            size_t tb = ((size_t)tile * 4) * 128 + tid;
            float s = b2[e] + g_scorePart[tb] + g_scorePart[tb + 128]
                    + g_scorePart[tb + 256] + g_scorePart[tb + 384];
            wt = expf(s);      // |s| small; no max-subtraction needed
            sN[tid] = g_perm[tbase + tid];
        } else sN[tid] = 0;
        sWt[tid] = wt;
        if (blockIdx.y == 0) {
            float v = wt;
#pragma unroll
            for (int o = 16; o; o >>= 1) v += __shfl_xor_sync(~0u, v, o);
            if ((tid & 31) == 0) sSum[tid >> 5] = v;
        }
    }
    __syncthreads();
    if (blockIdx.y == 0 && tid == 0)
        g_wtsum[tile] = (sSum[0] + sSum[1]) + (sSum[2] + sSum[3]);

    int dh = blockIdx.y * 128 + tid;  // half2 index: 256 floats per y-block
    // fixed-trip loop (padded wt=0), 4 accumulators for ILP
    float2 a0 = make_float2(0.f, 0.f), a1 = a0, a2 = a0, a3 = a0;
#pragma unroll
    for (int t = 0; t < TILE_T; t += 4) {
        float2 f0 = __half22float2(((const __half2*)(g_xh + (size_t)sN[t]     * DIM))[dh]);
        float2 f1 = __half22float2(((const __half2*)(g_xh + (size_t)sN[t + 1] * DIM))[dh]);
        float2 f2 = __half22float2(((const __half2*)(g_xh + (size_t)sN[t + 2] * DIM))[dh]);
        float2 f3 = __half22float2(((const __half2*)(g_xh + (size_t)sN[t + 3] * DIM))[dh]);
        a0.x = fmaf(sWt[t],     f0.x, a0.x); a0.y = fmaf(sWt[t],     f0.y, a0.y);
        a1.x = fmaf(sWt[t + 1], f1.x, a1.x); a1.y = fmaf(sWt[t + 1], f1.y, a1.y);
        a2.x = fmaf(sWt[t + 2], f2.x, a2.x); a2.y = fmaf(sWt[t + 2], f2.y, a2.y);
        a3.x = fmaf(sWt[t + 3], f3.x, a3.x); a3.y = fmaf(sWt[t + 3], f3.y, a3.y);
    }
    float2 acc = make_float2((a0.x + a1.x) + (a2.x + a3.x),
                             (a0.y + a1.y) + (a2.y + a3.y));
    ((float2*)g_partial)[(size_t)tile * (DIM / 2) + dh] = acc;
}

// ---------------- K7: fixed-order reduce + normalize -> output ---------------
__global__ void k_poolB(float* __restrict__ out) {
    int e = blockIdx.x;
    int d = threadIdx.x;  // 1024
    // compute this expert's tile range from g_count
    int t0 = 0, t1 = 0, idx = 0;
#pragma unroll
    for (int k = 0; k < 8; k++) {
        int t = (g_count[k] + TILE_T - 1) >> 7;
        if (k == e) { t0 = idx; t1 = idx + t; }
        idx += t;
    }
    float acc = 0.f, wsum = 0.f;
    for (int t = t0; t < t1; t++) {
        acc  += g_partial[(size_t)t * DIM + d];
        wsum += g_wtsum[t];
    }
    out[e * DIM + d] = (wsum > 0.f) ? acc / wsum : 0.f;
}

// ---------------- entry ------------------------------------------------------
extern "C" void kernel_launch(void* const* d_in, const int* in_sizes, int n_in,
                              void* d_out, int out_size) {
    const float* x   = (const float*)d_in[0];
    const float* gw  = (const float*)d_in[1];
    const float* W1  = (const float*)d_in[2];
    const float* b1  = (const float*)d_in[3];
    const float* w2  = (const float*)d_in[4];
    const float* b2  = (const float*)d_in[5];
    float* out = (float*)d_out;

    cudaFuncSetAttribute(k_score, cudaFuncAttributeMaxDynamicSharedMemorySize, SMTOT);

    k_gateCvt<<<GB + 128, 256>>>(x, gw, W1);
    k_scatter<<<GB, 256>>>();
    k_score<<<dim3(MAXTILES, 4), 256, SMTOT>>>(b1, w2);
    k_poolA<<<dim3(MAXTILES, 4), 128>>>(b2);
    k_poolB<<<8, 1024>>>(out);
}

// round 11
// speedup vs baseline: 2.1197x; 1.0002x over previous
#include <cuda_runtime.h>
#include <cuda_fp16.h>
#include <cstdint>

#define NTOK 32768
#define DIM  1024
#define HID  512
#define NEXP 8
#define TILE_T 128
#define MAXTILES 264   // 32768/128 + 8
#define GB 256         // gate blocks
#define GT 128         // tokens per gate block

// ---------------- scratch (device globals; no allocations allowed) ----------
__device__ int   g_sel[NTOK];
__device__ int   g_blockHist[GB][8];
__device__ int   g_count[8];
__device__ int   g_perm[NTOK + NEXP * TILE_T];
__device__ float g_scorePart[(size_t)MAXTILES * 4 * 128];
__device__ float g_wtsum[MAXTILES];
__device__ float g_partial[(size_t)MAXTILES * DIM];
__device__ __half g_xh[(size_t)NTOK * DIM];
__device__ __half g_w1h[(size_t)NEXP * HID * DIM];

// ---------------- PTX helpers (all sm_80-era; no 'a' features) --------------
__device__ __forceinline__ uint32_t smem_u32(const void* p) {
    uint32_t a;
    asm("{ .reg .u64 t; cvta.to.shared.u64 t, %1; cvt.u32.u64 %0, t; }" : "=r"(a) : "l"(p));
    return a;
}
#define SW128(o) (((uint32_t)(o)) ^ ((((uint32_t)(o)) >> 3) & 0x70))

#define CPA16(dst, src) \
    asm volatile("cp.async.cg.shared.global [%0], [%1], 16;" :: "r"(dst), "l"(src))

#define LDSM4(r, addr) \
    asm volatile("ldmatrix.sync.aligned.m8n8.x4.shared.b16 {%0,%1,%2,%3}, [%4];" \
        : "=r"((r)[0]), "=r"((r)[1]), "=r"((r)[2]), "=r"((r)[3]) : "r"(addr))

#define MMA_F16(d, a, b) \
    asm volatile("mma.sync.aligned.m16n8k16.row.col.f32.f16.f16.f32 " \
        "{%0,%1,%2,%3}, {%4,%5,%6,%7}, {%8,%9}, {%0,%1,%2,%3};" \
        : "+f"((d)[0]), "+f"((d)[1]), "+f"((d)[2]), "+f"((d)[3]) \
        : "r"((a)[0]), "r"((a)[1]), "r"((a)[2]), "r"((a)[3]), \
          "r"((b)[0]), "r"((b)[1]))

// ---------------- inline tile descriptor from g_count ------------------------
struct TInfo { int e, tbase, tvalid, ntiles; };
__device__ __forceinline__ TInfo tile_info(int tile) {
    TInfo r; r.e = -1; r.tbase = 0; r.tvalid = 0;
    int idx = 0, pad = 0;
#pragma unroll
    for (int k = 0; k < 8; k++) {
        int c = g_count[k];
        int t = (c + TILE_T - 1) >> 7;
        if (r.e < 0 && tile < idx + t) {
            int li = tile - idx;
            r.e = k;
            r.tbase = pad + (li << 7);
            r.tvalid = min(TILE_T, c - (li << 7));
        }
        idx += t; pad += t << 7;
    }
    r.ntiles = idx;
    if (r.e < 0) r.e = 0;
    return r;
}

// ---------------- K1: fused gate (+x->fp16) and W1 convert/transpose --------
__global__ void __launch_bounds__(256)
k_gateCvt(const float* __restrict__ x, const float* __restrict__ gw,
          const float* __restrict__ W1) {
    if (blockIdx.x < GB) {
        __shared__ float4 sG4[NEXP * 256];   // 32 KB
        __shared__ int sHist[8];
        int tid = threadIdx.x;
        if (tid < 8) sHist[tid] = 0;
        const float4* g4 = (const float4*)gw;
#pragma unroll
        for (int i = 0; i < 8; i++) sG4[tid + i * 256] = g4[tid + i * 256];
        __syncthreads();

        int warp = tid >> 5, lane = tid & 31;
        int base = blockIdx.x * GT + warp * (GT / 8);

        float4 cur[8], nxt[8];
        {
            const float4* xr4 = (const float4*)(x + (size_t)base * DIM);
#pragma unroll
            for (int j = 0; j < 8; j++) cur[j] = xr4[j * 32 + lane];
        }
        for (int it = 0; it < GT / 8; it++) {
            int n = base + it;
            if (it + 1 < GT / 8) {   // prefetch next token row first
                const float4* xr4 = (const float4*)(x + (size_t)(n + 1) * DIM);
#pragma unroll
                for (int j = 0; j < 8; j++) nxt[j] = xr4[j * 32 + lane];
            }
            uint2* xhr = (uint2*)(g_xh + (size_t)n * DIM);
#pragma unroll
            for (int j = 0; j < 8; j++) {
                __half2 h0 = __floats2half2_rn(cur[j].x, cur[j].y);
                __half2 h1 = __floats2half2_rn(cur[j].z, cur[j].w);
                xhr[j * 32 + lane] = make_uint2(*(uint32_t*)&h0, *(uint32_t*)&h1);
            }
            float acc[8];
#pragma unroll
            for (int e = 0; e < 8; e++) acc[e] = 0.f;
#pragma unroll
            for (int j = 0; j < 8; j++)
#pragma unroll
                for (int e = 0; e < 8; e++) {
                    float4 g = sG4[e * 256 + j * 32 + lane];
                    acc[e] += cur[j].x * g.x + cur[j].y * g.y
                            + cur[j].z * g.z + cur[j].w * g.w;
                }
#pragma unroll
            for (int e = 0; e < 8; e++)
#pragma unroll
                for (int o = 16; o; o >>= 1) acc[e] += __shfl_xor_sync(~0u, acc[e], o);
            if (lane == 0) {
                int best = 0; float bv = acc[0];
#pragma unroll
                for (int e = 1; e < 8; e++) if (acc[e] > bv) { bv = acc[e]; best = e; }
                g_sel[n] = best;
                atomicAdd(&sHist[best], 1);
            }
#pragma unroll
            for (int j = 0; j < 8; j++) cur[j] = nxt[j];
        }
        __syncthreads();
        if (tid < 8) g_blockHist[blockIdx.x][tid] = sHist[tid];
    } else {
        // ---- W1 convert + transpose: 4096 32x32 tiles / 128 blocks ----
        __shared__ float t[32][33];
        int bid = blockIdx.x - GB;
        int tid = threadIdx.x;
        for (int k = 0; k < 32; k++) {
            int tileId = bid * 32 + k;
            int e  = tileId >> 9;
            int rem = tileId & 511;
            int db = rem >> 4, hb = rem & 15;
            const float* src = W1 + ((size_t)e * DIM + db * 32) * HID + hb * 32;
            {   // 256 threads load 32 rows x 8 float4
                int row = tid >> 3, c4 = (tid & 7) * 4;
                float4 v = *(const float4*)(src + (size_t)row * HID + c4);
                t[row][c4] = v.x; t[row][c4 + 1] = v.y;
                t[row][c4 + 2] = v.z; t[row][c4 + 3] = v.w;
            }
            __syncthreads();
            {   // paired half2 stores: d-pair = 2*(tid&15), h = tid>>4 + j*16
                int dp = (tid & 15) * 2, hh = tid >> 4;
#pragma unroll
                for (int j = 0; j < 2; j++) {
                    int h = hh + j * 16;
                    __half2 hv = __floats2half2_rn(t[dp][h], t[dp + 1][h]);
                    size_t o = ((size_t)e * HID + hb * 32 + h) * DIM + db * 32 + dp;
                    *(__half2*)(g_w1h + o) = hv;
                }
            }
            __syncthreads();
        }
    }
}

// ---------------- K3: scatter with per-block local scan ----------------------
__global__ void __launch_bounds__(256)
k_scatter() {
    __shared__ int sSel[GT];
    __shared__ int sCnt[8], sPre[8], sOffE[8];
    int tid = threadIdx.x, warp = tid >> 5, lane = tid & 31;
    int b = blockIdx.x;

    if (tid < GT) sSel[tid] = g_sel[b * GT + tid];

    {
        int tot = 0, pre = 0;
#pragma unroll
        for (int j = 0; j < 8; j++) {
            int bb = lane + j * 32;
            int h = g_blockHist[bb][warp];
            tot += h;
            pre += (bb < b) ? h : 0;
        }
#pragma unroll
        for (int o = 16; o; o >>= 1) {
            tot += __shfl_xor_sync(~0u, tot, o);
            pre += __shfl_xor_sync(~0u, pre, o);
        }
        if (lane == 0) { sCnt[warp] = tot; sPre[warp] = pre; }
    }
    __syncthreads();
    if (tid == 0) {
        int pad = 0;
#pragma unroll
        for (int e = 0; e < 8; e++) {
            sOffE[e] = pad + sPre[e];
            if (b == 0) g_count[e] = sCnt[e];
            pad += ((sCnt[e] + TILE_T - 1) >> 7) << 7;
        }
    }
    __syncthreads();
    if (tid < GT) {
        int e = sSel[tid];
        int rank = 0;
        for (int i = 0; i < tid; i++) rank += (sSel[i] == e);
        g_perm[sOffE[e] + rank] = b * GT + tid;
    }
}

// ---------------- K4: score GEMM on HMMA, 3-stage, single-sync loop ---------
#define KC 64
#define SMX 0         // 3 stages x 16KB
#define SMW 49152     // 3 stages x 16KB
#define SMB1 98304
#define SMW2 98816
#define SMRED 99328
#define SMTOK 100352
#define SMTOT 100864

__device__ __forceinline__ void load_chunk(uint32_t smb, const int* sTok,
                                           const char* xB, const char* wB,
                                           int d0, int stage, int tid) {
#pragma unroll
    for (int it = 0; it < 4; it++) {
        int seg = it * 256 + tid;           // 0..1023
        int row = seg >> 3, c16 = seg & 7;  // 16B column block
        uint32_t doff = SW128((uint32_t)(row * 128 + c16 * 16));
        size_t xsrc = (size_t)sTok[row] * (DIM * 2) + d0 * 2 + c16 * 16;
        CPA16(smb + SMX + stage * 16384 + doff, xB + xsrc);
        size_t wsrc = (size_t)row * (DIM * 2) + d0 * 2 + c16 * 16;
        CPA16(smb + SMW + stage * 16384 + doff, wB + wsrc);
    }
    asm volatile("cp.async.commit_group;" ::: "memory");
}

__global__ void __launch_bounds__(256, 2)
k_score(const float* __restrict__ b1, const float* __restrict__ w2) {
    int tile = blockIdx.x;
    TInfo ti = tile_info(tile);
    if (tile >= ti.ntiles) return;
    int nc = blockIdx.y;
    int e = ti.e, tbase = ti.tbase, tvalid = ti.tvalid;

    extern __shared__ char sm[];
    uint32_t smb = smem_u32(sm);
    int tid = threadIdx.x, wid = tid >> 5, lane = tid & 31;

    int*   sTok = (int*)(sm + SMTOK);
    float* b1s  = (float*)(sm + SMB1);
    float* w2s  = (float*)(sm + SMW2);
    float* sRed = (float*)(sm + SMRED);

    if (tid < 128) {
        sTok[tid] = g_perm[tbase + min(tid, tvalid - 1)];
        int h = nc * 128 + tid;
        b1s[tid] = b1[e * HID + h];
        w2s[tid] = w2[e * HID + h];
    }
    __syncthreads();

    const char* xB = (const char*)g_xh;
    const char* wB = (const char*)(g_w1h + ((size_t)e * HID + (size_t)nc * 128) * DIM);

    int wm = wid >> 1, wn = wid & 1;
    int m0 = wm * 32, n0 = wn * 64;

    uint32_t aBase  = (uint32_t)((m0 + (lane & 15)) * 128 + (lane >> 4) * 16);
    uint32_t bBase4 = (uint32_t)((n0 + (lane >> 4) * 8 + (lane & 7)) * 128 +
                                 ((lane >> 3) & 1) * 16);

    float acc[2][8][4];
#pragma unroll
    for (int mt = 0; mt < 2; mt++)
#pragma unroll
        for (int nt = 0; nt < 8; nt++)
#pragma unroll
            for (int j = 0; j < 4; j++) acc[mt][nt][j] = 0.f;

    load_chunk(smb, sTok, xB, wB, 0, 0, tid);
    load_chunk(smb, sTok, xB, wB, KC, 1, tid);

    for (int i = 0; i < 16; i++) {
        if (i < 15) {
            asm volatile("cp.async.wait_group 1;" ::: "memory");
        } else {
            asm volatile("cp.async.wait_group 0;" ::: "memory");
        }
        __syncthreads();
        // all warps past compute of stage i-1 -> safe to overwrite it
        if (i + 2 < 16)
            load_chunk(smb, sTok, xB, wB, (i + 2) * KC, (i + 2) % 3, tid);

        uint32_t xs = smb + SMX + (i % 3) * 16384;
        uint32_t ws = smb + SMW + (i % 3) * 16384;
#pragma unroll
        for (int kk = 0; kk < 4; kk++) {
            uint32_t a[2][4];
#pragma unroll
            for (int mt = 0; mt < 2; mt++)
                LDSM4(a[mt], xs + SW128(aBase + mt * 2048 + kk * 32));
#pragma unroll
            for (int nt2 = 0; nt2 < 4; nt2++) {
                uint32_t b4[4];
                LDSM4(b4, ws + SW128(bBase4 + nt2 * 2048 + kk * 32));
#pragma unroll
                for (int mt = 0; mt < 2; mt++) {
                    MMA_F16(acc[mt][nt2 * 2],     a[mt], b4);
                    MMA_F16(acc[mt][nt2 * 2 + 1], a[mt], b4 + 2);
                }
            }
        }
    }

    // epilogue: +b1, tanh, dot w2 over this CTA's 128 h-cols
    int g = lane >> 2, qc = lane & 3;
    float rs[4] = {0.f, 0.f, 0.f, 0.f};
#pragma unroll
    for (int mt = 0; mt < 2; mt++)
#pragma unroll
        for (int nt = 0; nt < 8; nt++) {
            int hl = wn * 64 + nt * 8 + qc * 2;
            float w20 = w2s[hl], w21 = w2s[hl + 1];
            float bb0 = b1s[hl], bb1 = b1s[hl + 1];
            rs[mt * 2 + 0] += tanhf(acc[mt][nt][0] + bb0) * w20
                            + tanhf(acc[mt][nt][1] + bb1) * w21;
            rs[mt * 2 + 1] += tanhf(acc[mt][nt][2] + bb0) * w20
                            + tanhf(acc[mt][nt][3] + bb1) * w21;
        }
#pragma unroll
    for (int j = 0; j < 4; j++) {
        rs[j] += __shfl_xor_sync(~0u, rs[j], 1);
        rs[j] += __shfl_xor_sync(~0u, rs[j], 2);
    }
    __syncthreads();
    if (qc == 0) {
        sRed[wn * 128 + m0 + g]      = rs[0];
        sRed[wn * 128 + m0 + g + 8]  = rs[1];
        sRed[wn * 128 + m0 + g + 16] = rs[2];
        sRed[wn * 128 + m0 + g + 24] = rs[3];
    }
    __syncthreads();
    if (tid < 128)
        g_scorePart[((size_t)tile * 4 + nc) * 128 + tid] = sRed[tid] + sRed[128 + tid];
}

// ---------------- K6: pooled partials, softmax-free (raw exp weights) --------
__global__ void __launch_bounds__(128)
k_poolA(const float* __restrict__ b2) {
    int tile = blockIdx.x;
    TInfo ti = tile_info(tile);
    if (tile >= ti.ntiles) return;
    int e = ti.e, tbase = ti.tbase, tvalid = ti.tvalid;
    __shared__ float sWt[TILE_T];
    __shared__ int   sN[TILE_T];
    __shared__ float sSum[4];
    int tid = threadIdx.x;  // 128
    {
        float wt = 0.f;
        if (tid < tvalid) {
            size_t tb = ((size_t)tile * 4) * 128 + tid;
            float s = b2[e] + g_scorePart[tb] + g_scorePart[tb + 128]
                    + g_scorePart[tb + 256] + g_scorePart[tb + 384];
            wt = expf(s);      // |s| small; no max-subtraction needed
            sN[tid] = g_perm[tbase + tid];
        } else sN[tid] = 0;
        sWt[tid] = wt;
        if (blockIdx.y == 0) {
            float v = wt;
#pragma unroll
            for (int o = 16; o; o >>= 1) v += __shfl_xor_sync(~0u, v, o);
            if ((tid & 31) == 0) sSum[tid >> 5] = v;
        }
    }
    __syncthreads();
    if (blockIdx.y == 0 && tid == 0)
        g_wtsum[tile] = (sSum[0] + sSum[1]) + (sSum[2] + sSum[3]);

    int dh = blockIdx.y * 128 + tid;  // half2 index
    float2 a0 = make_float2(0.f, 0.f), a1 = a0, a2 = a0, a3 = a0;
#pragma unroll
    for (int t = 0; t < TILE_T; t += 4) {
        float2 f0 = __half22float2(((const __half2*)(g_xh + (size_t)sN[t]     * DIM))[dh]);
        float2 f1 = __half22float2(((const __half2*)(g_xh + (size_t)sN[t + 1] * DIM))[dh]);
        float2 f2 = __half22float2(((const __half2*)(g_xh + (size_t)sN[t + 2] * DIM))[dh]);
        float2 f3 = __half22float2(((const __half2*)(g_xh + (size_t)sN[t + 3] * DIM))[dh]);
        a0.x = fmaf(sWt[t],     f0.x, a0.x); a0.y = fmaf(sWt[t],     f0.y, a0.y);
        a1.x = fmaf(sWt[t + 1], f1.x, a1.x); a1.y = fmaf(sWt[t + 1], f1.y, a1.y);
        a2.x = fmaf(sWt[t + 2], f2.x, a2.x); a2.y = fmaf(sWt[t + 2], f2.y, a2.y);
        a3.x = fmaf(sWt[t + 3], f3.x, a3.x); a3.y = fmaf(sWt[t + 3], f3.y, a3.y);
    }
    float2 acc = make_float2((a0.x + a1.x) + (a2.x + a3.x),
                             (a0.y + a1.y) + (a2.y + a3.y));
    ((float2*)g_partial)[(size_t)tile * (DIM / 2) + dh] = acc;
}

// ---------------- K7: fixed-order reduce + normalize -> output ---------------
__global__ void k_poolB(float* __restrict__ out) {
    int e = blockIdx.x;
    int d = threadIdx.x;  // 1024
    int t0 = 0, t1 = 0, idx = 0;
#pragma unroll
    for (int k = 0; k < 8; k++) {
        int t = (g_count[k] + TILE_T - 1) >> 7;
        if (k == e) { t0 = idx; t1 = idx + t; }
        idx += t;
    }
    float acc = 0.f, wsum = 0.f;
    for (int t = t0; t < t1; t++) {
        acc  += g_partial[(size_t)t * DIM + d];
        wsum += g_wtsum[t];
    }
    out[e * DIM + d] = (wsum > 0.f) ? acc / wsum : 0.f;
}

// ---------------- entry ------------------------------------------------------
extern "C" void kernel_launch(void* const* d_in, const int* in_sizes, int n_in,
                              void* d_out, int out_size) {
    const float* x   = (const float*)d_in[0];
    const float* gw  = (const float*)d_in[1];
    const float* W1  = (const float*)d_in[2];
    const float* b1  = (const float*)d_in[3];
    const float* w2  = (const float*)d_in[4];
    const float* b2  = (const float*)d_in[5];
    float* out = (float*)d_out;

    cudaFuncSetAttribute(k_score, cudaFuncAttributeMaxDynamicSharedMemorySize, SMTOT);

    k_gateCvt<<<GB + 128, 256>>>(x, gw, W1);
    k_scatter<<<GB, 256>>>();
    k_score<<<dim3(MAXTILES, 4), 256, SMTOT>>>(b1, w2);
    k_poolA<<<dim3(MAXTILES, 4), 128>>>(b2);
    k_poolB<<<8, 1024>>>(out);
}

// round 12
// speedup vs baseline: 2.6649x; 1.2572x over previous
#include <cuda_runtime.h>
#include <cuda_fp16.h>
#include <cstdint>

#define NTOK 32768
#define DIM  1024
#define HID  512
#define NEXP 8
#define TILE_T 128
#define MAXTILES 264   // 32768/128 + 8
#define GB 256         // gate blocks
#define GT 128         // tokens per gate block

// ---------------- scratch (device globals; no allocations allowed) ----------
__device__ int   g_sel[NTOK];
__device__ int   g_blockHist[GB][8];
__device__ int   g_count[8];
__device__ int   g_perm[NTOK + NEXP * TILE_T];
__device__ float g_scorePart[(size_t)MAXTILES * 4 * 128];
__device__ float g_wtsum[MAXTILES];
__device__ float g_partial[(size_t)MAXTILES * DIM];
__device__ __half g_xh[(size_t)NTOK * DIM];
__device__ __half g_w1h[(size_t)NEXP * HID * DIM];

// ---------------- PTX helpers (all sm_80-era; no 'a' features) --------------
__device__ __forceinline__ uint32_t smem_u32(const void* p) {
    uint32_t a;
    asm("{ .reg .u64 t; cvta.to.shared.u64 t, %1; cvt.u32.u64 %0, t; }" : "=r"(a) : "l"(p));
    return a;
}
#define SW128(o) (((uint32_t)(o)) ^ ((((uint32_t)(o)) >> 3) & 0x70))

#define CPA16(dst, src) \
    asm volatile("cp.async.cg.shared.global [%0], [%1], 16;" :: "r"(dst), "l"(src))

#define LDSM4(r, addr) \
    asm volatile("ldmatrix.sync.aligned.m8n8.x4.shared.b16 {%0,%1,%2,%3}, [%4];" \
        : "=r"((r)[0]), "=r"((r)[1]), "=r"((r)[2]), "=r"((r)[3]) : "r"(addr))

#define MMA_F16(d, a, b) \
    asm volatile("mma.sync.aligned.m16n8k16.row.col.f32.f16.f16.f32 " \
        "{%0,%1,%2,%3}, {%4,%5,%6,%7}, {%8,%9}, {%0,%1,%2,%3};" \
        : "+f"((d)[0]), "+f"((d)[1]), "+f"((d)[2]), "+f"((d)[3]) \
        : "r"((a)[0]), "r"((a)[1]), "r"((a)[2]), "r"((a)[3]), \
          "r"((b)[0]), "r"((b)[1]))

// ---------------- inline tile descriptor from g_count ------------------------
struct TInfo { int e, tbase, tvalid, ntiles; };
__device__ __forceinline__ TInfo tile_info(int tile) {
    TInfo r; r.e = -1; r.tbase = 0; r.tvalid = 0;
    int idx = 0, pad = 0;
#pragma unroll
    for (int k = 0; k < 8; k++) {
        int c = g_count[k];
        int t = (c + TILE_T - 1) >> 7;
        if (r.e < 0 && tile < idx + t) {
            int li = tile - idx;
            r.e = k;
            r.tbase = pad + (li << 7);
            r.tvalid = min(TILE_T, c - (li << 7));
        }
        idx += t; pad += t << 7;
    }
    r.ntiles = idx;
    if (r.e < 0) r.e = 0;
    return r;
}

// ---------------- K1: fused gate (+x->fp16) and W1 convert/transpose --------
__global__ void __launch_bounds__(256)
k_gateCvt(const float* __restrict__ x, const float* __restrict__ gw,
          const float* __restrict__ W1) {
    if (blockIdx.x < GB) {
        __shared__ float4 sG4[NEXP * 256];   // 32 KB
        __shared__ int sHist[8];
        int tid = threadIdx.x;
        if (tid < 8) sHist[tid] = 0;
        const float4* g4 = (const float4*)gw;
#pragma unroll
        for (int i = 0; i < 8; i++) sG4[tid + i * 256] = g4[tid + i * 256];
        __syncthreads();

        int warp = tid >> 5, lane = tid & 31;
        int base = blockIdx.x * GT + warp * (GT / 8);

        // 4-token groups; gate weights loaded once per group (4x smem reuse)
        for (int grp = 0; grp < 4; grp++) {
            int n0 = base + grp * 4;
            float acc[4][8];
#pragma unroll
            for (int t = 0; t < 4; t++)
#pragma unroll
                for (int e = 0; e < 8; e++) acc[t][e] = 0.f;

#pragma unroll
            for (int jh = 0; jh < 2; jh++) {   // j-halves keep regs bounded
                float4 cur[4][4];
#pragma unroll
                for (int t = 0; t < 4; t++) {
                    const float4* xr4 = (const float4*)(x + (size_t)(n0 + t) * DIM);
#pragma unroll
                    for (int j = 0; j < 4; j++)
                        cur[t][j] = xr4[(jh * 4 + j) * 32 + lane];
                }
#pragma unroll
                for (int t = 0; t < 4; t++) {
                    uint2* xhr = (uint2*)(g_xh + (size_t)(n0 + t) * DIM);
#pragma unroll
                    for (int j = 0; j < 4; j++) {
                        __half2 h0 = __floats2half2_rn(cur[t][j].x, cur[t][j].y);
                        __half2 h1 = __floats2half2_rn(cur[t][j].z, cur[t][j].w);
                        xhr[(jh * 4 + j) * 32 + lane] =
                            make_uint2(*(uint32_t*)&h0, *(uint32_t*)&h1);
                    }
                }
#pragma unroll
                for (int j = 0; j < 4; j++)
#pragma unroll
                    for (int e = 0; e < 8; e++) {
                        float4 g = sG4[e * 256 + (jh * 4 + j) * 32 + lane];
#pragma unroll
                        for (int t = 0; t < 4; t++)
                            acc[t][e] += cur[t][j].x * g.x + cur[t][j].y * g.y
                                       + cur[t][j].z * g.z + cur[t][j].w * g.w;
                    }
            }
#pragma unroll
            for (int t = 0; t < 4; t++) {
#pragma unroll
                for (int e = 0; e < 8; e++)
#pragma unroll
                    for (int o = 16; o; o >>= 1)
                        acc[t][e] += __shfl_xor_sync(~0u, acc[t][e], o);
                if (lane == 0) {
                    int best = 0; float bv = acc[t][0];
#pragma unroll
                    for (int e = 1; e < 8; e++)
                        if (acc[t][e] > bv) { bv = acc[t][e]; best = e; }
                    g_sel[n0 + t] = best;
                    atomicAdd(&sHist[best], 1);
                }
            }
        }
        __syncthreads();
        if (tid < 8) g_blockHist[blockIdx.x][tid] = sHist[tid];
    } else {
        // ---- W1 convert + transpose: 4096 32x32 tiles / 128 blocks ----
        __shared__ float t[32][33];
        int bid = blockIdx.x - GB;
        int tid = threadIdx.x;
        for (int k = 0; k < 32; k++) {
            int tileId = bid * 32 + k;
            int e  = tileId >> 9;
            int rem = tileId & 511;
            int db = rem >> 4, hb = rem & 15;
            const float* src = W1 + ((size_t)e * DIM + db * 32) * HID + hb * 32;
            {
                int row = tid >> 3, c4 = (tid & 7) * 4;
                float4 v = *(const float4*)(src + (size_t)row * HID + c4);
                t[row][c4] = v.x; t[row][c4 + 1] = v.y;
                t[row][c4 + 2] = v.z; t[row][c4 + 3] = v.w;
            }
            __syncthreads();
            {
                int dp = (tid & 15) * 2, hh = tid >> 4;
#pragma unroll
                for (int j = 0; j < 2; j++) {
                    int h = hh + j * 16;
                    __half2 hv = __floats2half2_rn(t[dp][h], t[dp + 1][h]);
                    size_t o = ((size_t)e * HID + hb * 32 + h) * DIM + db * 32 + dp;
                    *(__half2*)(g_w1h + o) = hv;
                }
            }
            __syncthreads();
        }
    }
}

// ---------------- K3: scatter with per-block local scan ----------------------
__global__ void __launch_bounds__(256)
k_scatter() {
    __shared__ int sSel[GT];
    __shared__ int sCnt[8], sPre[8], sOffE[8];
    int tid = threadIdx.x, warp = tid >> 5, lane = tid & 31;
    int b = blockIdx.x;

    if (tid < GT) sSel[tid] = g_sel[b * GT + tid];

    {
        int tot = 0, pre = 0;
#pragma unroll
        for (int j = 0; j < 8; j++) {
            int bb = lane + j * 32;
            int h = g_blockHist[bb][warp];
            tot += h;
            pre += (bb < b) ? h : 0;
        }
#pragma unroll
        for (int o = 16; o; o >>= 1) {
            tot += __shfl_xor_sync(~0u, tot, o);
            pre += __shfl_xor_sync(~0u, pre, o);
        }
        if (lane == 0) { sCnt[warp] = tot; sPre[warp] = pre; }
    }
    __syncthreads();
    if (tid == 0) {
        int pad = 0;
#pragma unroll
        for (int e = 0; e < 8; e++) {
            sOffE[e] = pad + sPre[e];
            if (b == 0) g_count[e] = sCnt[e];
            pad += ((sCnt[e] + TILE_T - 1) >> 7) << 7;
        }
    }
    __syncthreads();
    if (tid < GT) {
        int e = sSel[tid];
        int rank = 0;
        for (int i = 0; i < tid; i++) rank += (sSel[i] == e);
        g_perm[sOffE[e] + rank] = b * GT + tid;
    }
}

// ---------------- K4: score GEMM on HMMA, 3-stage, single-sync loop ---------
#define KC 64
#define SMX 0         // 3 stages x 16KB
#define SMW 49152     // 3 stages x 16KB
#define SMB1 98304
#define SMW2 98816
#define SMRED 99328
#define SMTOK 100352
#define SMTOT 100864

__device__ __forceinline__ void load_chunk(uint32_t smb, const int* sTok,
                                           const char* xB, const char* wB,
                                           int d0, int stage, int tid) {
#pragma unroll
    for (int it = 0; it < 4; it++) {
        int seg = it * 256 + tid;           // 0..1023
        int row = seg >> 3, c16 = seg & 7;  // 16B column block
        uint32_t doff = SW128((uint32_t)(row * 128 + c16 * 16));
        size_t xsrc = (size_t)sTok[row] * (DIM * 2) + d0 * 2 + c16 * 16;
        CPA16(smb + SMX + stage * 16384 + doff, xB + xsrc);
        size_t wsrc = (size_t)row * (DIM * 2) + d0 * 2 + c16 * 16;
        CPA16(smb + SMW + stage * 16384 + doff, wB + wsrc);
    }
    asm volatile("cp.async.commit_group;" ::: "memory");
}

__global__ void __launch_bounds__(256, 2)
k_score(const float* __restrict__ b1, const float* __restrict__ w2) {
    int tile = blockIdx.x;
    TInfo ti = tile_info(tile);
    if (tile >= ti.ntiles) return;
    int nc = blockIdx.y;
    int e = ti.e, tbase = ti.tbase, tvalid = ti.tvalid;

    extern __shared__ char sm[];
    uint32_t smb = smem_u32(sm);
    int tid = threadIdx.x, wid = tid >> 5, lane = tid & 31;

    int*   sTok = (int*)(sm + SMTOK);
    float* b1s  = (float*)(sm + SMB1);
    float* w2s  = (float*)(sm + SMW2);
    float* sRed = (float*)(sm + SMRED);

    if (tid < 128) {
        sTok[tid] = g_perm[tbase + min(tid, tvalid - 1)];
        int h = nc * 128 + tid;
        b1s[tid] = b1[e * HID + h];
        w2s[tid] = w2[e * HID + h];
    }
    __syncthreads();

    const char* xB = (const char*)g_xh;
    const char* wB = (const char*)(g_w1h + ((size_t)e * HID + (size_t)nc * 128) * DIM);

    int wm = wid >> 1, wn = wid & 1;
    int m0 = wm * 32, n0 = wn * 64;

    uint32_t aBase  = (uint32_t)((m0 + (lane & 15)) * 128 + (lane >> 4) * 16);
    uint32_t bBase4 = (uint32_t)((n0 + (lane >> 4) * 8 + (lane & 7)) * 128 +
                                 ((lane >> 3) & 1) * 16);

    float acc[2][8][4];
#pragma unroll
    for (int mt = 0; mt < 2; mt++)
#pragma unroll
        for (int nt = 0; nt < 8; nt++)
#pragma unroll
            for (int j = 0; j < 4; j++) acc[mt][nt][j] = 0.f;

    load_chunk(smb, sTok, xB, wB, 0, 0, tid);
    load_chunk(smb, sTok, xB, wB, KC, 1, tid);

    for (int i = 0; i < 16; i++) {
        if (i < 15) {
            asm volatile("cp.async.wait_group 1;" ::: "memory");
        } else {
            asm volatile("cp.async.wait_group 0;" ::: "memory");
        }
        __syncthreads();
        if (i + 2 < 16)
            load_chunk(smb, sTok, xB, wB, (i + 2) * KC, (i + 2) % 3, tid);

        uint32_t xs = smb + SMX + (i % 3) * 16384;
        uint32_t ws = smb + SMW + (i % 3) * 16384;
#pragma unroll
        for (int kk = 0; kk < 4; kk++) {
            uint32_t a[2][4];
#pragma unroll
            for (int mt = 0; mt < 2; mt++)
                LDSM4(a[mt], xs + SW128(aBase + mt * 2048 + kk * 32));
#pragma unroll
            for (int nt2 = 0; nt2 < 4; nt2++) {
                uint32_t b4[4];
                LDSM4(b4, ws + SW128(bBase4 + nt2 * 2048 + kk * 32));
#pragma unroll
                for (int mt = 0; mt < 2; mt++) {
                    MMA_F16(acc[mt][nt2 * 2],     a[mt], b4);
                    MMA_F16(acc[mt][nt2 * 2 + 1], a[mt], b4 + 2);
                }
            }
        }
    }

    // epilogue: +b1, tanh, dot w2 over this CTA's 128 h-cols
    int g = lane >> 2, qc = lane & 3;
    float rs[4] = {0.f, 0.f, 0.f, 0.f};
#pragma unroll
    for (int mt = 0; mt < 2; mt++)
#pragma unroll
        for (int nt = 0; nt < 8; nt++) {
            int hl = wn * 64 + nt * 8 + qc * 2;
            float w20 = w2s[hl], w21 = w2s[hl + 1];
            float bb0 = b1s[hl], bb1 = b1s[hl + 1];
            rs[mt * 2 + 0] += tanhf(acc[mt][nt][0] + bb0) * w20
                            + tanhf(acc[mt][nt][1] + bb1) * w21;
            rs[mt * 2 + 1] += tanhf(acc[mt][nt][2] + bb0) * w20
                            + tanhf(acc[mt][nt][3] + bb1) * w21;
        }
#pragma unroll
    for (int j = 0; j < 4; j++) {
        rs[j] += __shfl_xor_sync(~0u, rs[j], 1);
        rs[j] += __shfl_xor_sync(~0u, rs[j], 2);
    }
    __syncthreads();
    if (qc == 0) {
        sRed[wn * 128 + m0 + g]      = rs[0];
        sRed[wn * 128 + m0 + g + 8]  = rs[1];
        sRed[wn * 128 + m0 + g + 16] = rs[2];
        sRed[wn * 128 + m0 + g + 24] = rs[3];
    }
    __syncthreads();
    if (tid < 128)
        g_scorePart[((size_t)tile * 4 + nc) * 128 + tid] = sRed[tid] + sRed[128 + tid];
}

// ---------------- K6: pooled partials, softmax-free (raw exp weights) --------
__global__ void __launch_bounds__(128, 4)
k_poolA(const float* __restrict__ b2) {
    int tile = blockIdx.x;
    TInfo ti = tile_info(tile);
    if (tile >= ti.ntiles) return;
    int e = ti.e, tbase = ti.tbase, tvalid = ti.tvalid;
    __shared__ float sWt[TILE_T];
    __shared__ int   sN[TILE_T];
    __shared__ float sSum[4];
    int tid = threadIdx.x;  // 128
    {
        float wt = 0.f;
        if (tid < tvalid) {
            size_t tb = ((size_t)tile * 4) * 128 + tid;
            float s = b2[e] + g_scorePart[tb] + g_scorePart[tb + 128]
                    + g_scorePart[tb + 256] + g_scorePart[tb + 384];
            wt = expf(s);      // |s| small; no max-subtraction needed
            sN[tid] = g_perm[tbase + tid];
        } else sN[tid] = 0;
        sWt[tid] = wt;
        if (blockIdx.y == 0) {
            float v = wt;
#pragma unroll
            for (int o = 16; o; o >>= 1) v += __shfl_xor_sync(~0u, v, o);
            if ((tid & 31) == 0) sSum[tid >> 5] = v;
        }
    }
    __syncthreads();
    if (blockIdx.y == 0 && tid == 0)
        g_wtsum[tile] = (sSum[0] + sSum[1]) + (sSum[2] + sSum[3]);

    int dh = blockIdx.y * 128 + tid;  // half2 index
    float2 a0 = make_float2(0.f, 0.f), a1 = a0, a2 = a0, a3 = a0;
#pragma unroll 2
    for (int t = 0; t < TILE_T; t += 4) {
        float2 f0 = __half22float2(((const __half2*)(g_xh + (size_t)sN[t]     * DIM))[dh]);
        float2 f1 = __half22float2(((const __half2*)(g_xh + (size_t)sN[t + 1] * DIM))[dh]);
        float2 f2 = __half22float2(((const __half2*)(g_xh + (size_t)sN[t + 2] * DIM))[dh]);
        float2 f3 = __half22float2(((const __half2*)(g_xh + (size_t)sN[t + 3] * DIM))[dh]);
        a0.x = fmaf(sWt[t],     f0.x, a0.x); a0.y = fmaf(sWt[t],     f0.y, a0.y);
        a1.x = fmaf(sWt[t + 1], f1.x, a1.x); a1.y = fmaf(sWt[t + 1], f1.y, a1.y);
        a2.x = fmaf(sWt[t + 2], f2.x, a2.x); a2.y = fmaf(sWt[t + 2], f2.y, a2.y);
        a3.x = fmaf(sWt[t + 3], f3.x, a3.x); a3.y = fmaf(sWt[t + 3], f3.y, a3.y);
    }
    float2 acc = make_float2((a0.x + a1.x) + (a2.x + a3.x),
                             (a0.y + a1.y) + (a2.y + a3.y));
    ((float2*)g_partial)[(size_t)tile * (DIM / 2) + dh] = acc;
}

// ---------------- K7: fixed-order reduce + normalize -> output ---------------
__global__ void k_poolB(float* __restrict__ out) {
    int e = blockIdx.x;
    int d = threadIdx.x;  // 1024
    int t0 = 0, t1 = 0, idx = 0;
#pragma unroll
    for (int k = 0; k < 8; k++) {
        int t = (g_count[k] + TILE_T - 1) >> 7;
        if (k == e) { t0 = idx; t1 = idx + t; }
        idx += t;
    }
    float acc = 0.f, wsum = 0.f;
    for (int t = t0; t < t1; t++) {
        acc  += g_partial[(size_t)t * DIM + d];
        wsum += g_wtsum[t];
    }
    out[e * DIM + d] = (wsum > 0.f) ? acc / wsum : 0.f;
}

// ---------------- entry ------------------------------------------------------
extern "C" void kernel_launch(void* const* d_in, const int* in_sizes, int n_in,
                              void* d_out, int out_size) {
    const float* x   = (const float*)d_in[0];
    const float* gw  = (const float*)d_in[1];
    const float* W1  = (const float*)d_in[2];
    const float* b1  = (const float*)d_in[3];
    const float* w2  = (const float*)d_in[4];
    const float* b2  = (const float*)d_in[5];
    float* out = (float*)d_out;

    cudaFuncSetAttribute(k_score, cudaFuncAttributeMaxDynamicSharedMemorySize, SMTOT);

    k_gateCvt<<<GB + 128, 256>>>(x, gw, W1);
    k_scatter<<<GB, 256>>>();
    k_score<<<dim3(MAXTILES, 4), 256, SMTOT>>>(b1, w2);
    k_poolA<<<dim3(MAXTILES, 4), 128>>>(b2);
    k_poolB<<<8, 1024>>>(out);
}